// round 9
// baseline (speedup 1.0000x reference)
#include <cuda_runtime.h>
#include <cuda_fp16.h>
#include <cstdint>

#define B_ 16
#define S_ 577
#define SP 640               // padded seq (K padding for GEMM2)
#define E_ 1024
#define H_ 16
#define D_ 64
#define M_ (B_ * S_)         // 9232

// ---------------- scratch (static device globals, zero-init at load) -------
__device__ half g_Ah[(size_t)M_ * E_];                   // hidden fp16
__device__ half g_Wv[(size_t)E_ * E_];                   // v_w fp16
__device__ half g_Wo[(size_t)E_ * E_];                   // out_w fp16
__device__ half g_Vh[(size_t)H_ * E_ * SP];              // V^T [h][(b,d)][s] (pad=0)
__device__ half g_Ph[(size_t)H_ * S_ * SP];              // softmax(P) (pad=0)
__device__ half g_Oh[(size_t)M_ * E_];                   // attn out fp16

// ---------------- PTX helpers (portable sm_80-level) ------------------------
__device__ __forceinline__ uint32_t smem_u32(const void* p) {
    uint32_t a;
    asm("{ .reg .u64 t; cvta.to.shared.u64 t, %1; cvt.u32.u64 %0, t; }" : "=r"(a) : "l"(p));
    return a;
}
__device__ __forceinline__ void cp16(uint32_t dst, const void* src) {
    asm volatile("cp.async.cg.shared.global [%0], [%1], 16;" :: "r"(dst), "l"(src));
}
#define CP_COMMIT() asm volatile("cp.async.commit_group;" ::: "memory")
#define CP_WAIT2()  asm volatile("cp.async.wait_group 2;" ::: "memory")

__device__ __forceinline__ void ldsm4(uint32_t* r, uint32_t addr) {
    asm volatile("ldmatrix.sync.aligned.m8n8.x4.shared.b16 {%0,%1,%2,%3}, [%4];"
                 : "=r"(r[0]), "=r"(r[1]), "=r"(r[2]), "=r"(r[3]) : "r"(addr));
}
__device__ __forceinline__ void ldsm2(uint32_t* r, uint32_t addr) {
    asm volatile("ldmatrix.sync.aligned.m8n8.x2.shared.b16 {%0,%1}, [%2];"
                 : "=r"(r[0]), "=r"(r[1]) : "r"(addr));
}
__device__ __forceinline__ void mma_f16(float* c, const uint32_t* a, const uint32_t* b) {
    asm volatile("mma.sync.aligned.m16n8k16.row.col.f32.f16.f16.f32 "
                 "{%0,%1,%2,%3}, {%4,%5,%6,%7}, {%8,%9}, {%0,%1,%2,%3};"
                 : "+f"(c[0]), "+f"(c[1]), "+f"(c[2]), "+f"(c[3])
                 : "r"(a[0]), "r"(a[1]), "r"(a[2]), "r"(a[3]), "r"(b[0]), "r"(b[1]));
}

// ---------------- tiling ----------------------------------------------------
// ALL modes: CTA tile 64x128, KBLK=64, 3 CTAs/SM (24 warps -> latency hiding;
// round-8 ncu showed tensor=54% at 16 warps). Stage = A(8KB) + B(16KB) = 24KB,
// 3 stages = 72KB -> 3 CTAs = 216KB <= 228KB. Row = 8 x 16B chunks, physical
// chunk = c ^ (row&7): ldmatrix's 8 row-addresses -> 8 distinct chunks.
#define KBLK 64
#define NSTAGE 3
#define BM 64
#define A_BYTES (BM * 128)                   // 8192
#define STAGE_BYTES (A_BYTES + 16384)        // 24576
#define SMEM_SZ (NSTAGE * STAGE_BYTES)       // 73728
#define NCHUNK ((BM * 8 + 1024) / 256)       // 6 cp16 per thread per stage

__device__ __forceinline__ uint32_t swz(int row, int c) {
    return (uint32_t)(row * 128 + ((c ^ (row & 7)) << 4));
}

// ---------------------------------------------------------------------------
// fp16 HMMA GEMM, NT: C[m,n] = sum_k A[m,k]*B[n,k]
// MODE 0: V-proj   A=g_Ah, B=g_Wv, K=1024 -> g_Vh (V^T scatter, +v_b)
// MODE 1: P@V      A=g_Ph, B=g_Vh, K=640  -> g_Oh
// MODE 2: out-proj A=g_Oh, B=g_Wo, K=1024 -> d_out fp32 (+out_b)
// ---------------------------------------------------------------------------
template <int MODE>
__global__ __launch_bounds__(256, 3)
void gemm_hmma(const float* __restrict__ bias, float* __restrict__ outp)
{
    extern __shared__ __align__(1024) char smem[];
    const uint32_t sb = smem_u32(smem);
    const int tid  = threadIdx.x;
    const int wid  = tid >> 5, lane = tid & 31;
    const int wm   = wid & 1, wn = wid >> 1;      // warp grid 2m x 4n (32x32 warp tile)
    const int gid  = lane >> 2, tig = lane & 3;

    const half *Ah, *Bh;
    int Mrows, pitch, kiter;
    if (MODE == 0) {
        Ah = g_Ah; Bh = g_Wv;
        Mrows = M_; pitch = E_; kiter = E_ / KBLK;
    } else if (MODE == 1) {
        const size_t ho = (size_t)blockIdx.z;
        Ah = g_Ph + ho * S_ * SP;
        Bh = g_Vh + ho * E_ * SP;
        Mrows = S_; pitch = SP; kiter = SP / KBLK;
    } else {
        Ah = g_Oh; Bh = g_Wo;
        Mrows = M_; pitch = E_; kiter = E_ / KBLK;
    }
    const int tm0 = blockIdx.y * BM, tn0 = blockIdx.x * 128;

    auto do_load = [&](int kt) {
        if (kt < kiter) {
            const uint32_t sbase = sb + (uint32_t)(kt % NSTAGE) * STAGE_BYTES;
            const int koff = kt * KBLK;
#pragma unroll
            for (int p = 0; p < NCHUNK; p++) {
                const int id = p * 256 + tid;      // 0..1535
                if (id < BM * 8) {                 // A chunk
                    const int row = id >> 3, c = id & 7;
                    int grow = tm0 + row;
                    if (grow >= Mrows) grow = 0;   // clamp: never stored
                    cp16(sbase + swz(row, c),
                         Ah + (size_t)grow * pitch + koff + c * 8);
                } else {                           // B chunk (N=1024 exact)
                    const int idb = id - BM * 8;
                    const int row = idb >> 3, c = idb & 7;
                    cp16(sbase + (uint32_t)A_BYTES + swz(row, c),
                         Bh + (size_t)(tn0 + row) * pitch + koff + c * 8);
                }
            }
        }
        CP_COMMIT();
    };

    float acc[2][4][4];
#pragma unroll
    for (int i = 0; i < 2; i++)
#pragma unroll
        for (int j = 0; j < 4; j++)
#pragma unroll
            for (int q = 0; q < 4; q++) acc[i][j][q] = 0.f;

    do_load(0); do_load(1); do_load(2);

    for (int kt = 0; kt < kiter; kt++) {
        CP_WAIT2();
        __syncthreads();
        const uint32_t Ab = sb + (uint32_t)(kt % NSTAGE) * STAGE_BYTES;
        const uint32_t Bb = Ab + A_BYTES;

#pragma unroll
        for (int ks = 0; ks < 4; ks++) {           // 4 x k16 slices per k64
            uint32_t bf[4][2];
#pragma unroll
            for (int nt = 0; nt < 4; nt++) {
                const int nr = wn * 32 + nt * 8 + (lane & 7);
                const int c  = ks * 2 + ((lane >> 3) & 1);
                ldsm2(bf[nt], Bb + swz(nr, c));
            }
#pragma unroll
            for (int mt = 0; mt < 2; mt++) {
                uint32_t ah[4];
                {
                    const int mr = wm * 32 + mt * 16 + (lane & 15);
                    const int kh = lane >> 4;
                    ldsm4(ah, Ab + swz(mr, ks * 2 + kh));
                }
#pragma unroll
                for (int nt = 0; nt < 4; nt++)
                    mma_f16(acc[mt][nt], ah, bf[nt]);
            }
        }
        __syncthreads();
        do_load(kt + 3);
    }

    // ---------------- epilogue ----------------------------------------------
#pragma unroll
    for (int mt = 0; mt < 2; mt++) {
#pragma unroll
        for (int half_ = 0; half_ < 2; half_++) {
            const int m = tm0 + wm * 32 + mt * 16 + gid + half_ * 8;
            if (m >= Mrows) continue;
            int bb = 0, s = 0;
            if (MODE == 0) { bb = m / S_; s = m - bb * S_; }
#pragma unroll
            for (int nt = 0; nt < 4; nt++) {
                const int n0 = tn0 + wn * 32 + nt * 8 + tig * 2;
#pragma unroll
                for (int j = 0; j < 2; j++) {
                    const int n = n0 + j;
                    float v = acc[mt][nt][half_ * 2 + j];
                    if (MODE == 0) {
                        v += bias[n];
                        const size_t a = ((size_t)(n >> 6) * (B_ * D_)
                                          + (size_t)bb * D_ + (n & 63)) * SP + s;
                        g_Vh[a] = __float2half_rn(v);
                    } else if (MODE == 1) {
                        const size_t a = ((size_t)(n >> 6) * S_ + m) * E_
                                         + (size_t)blockIdx.z * D_ + (n & 63);
                        g_Oh[a] = __float2half_rn(v);
                    } else {
                        outp[(size_t)m * E_ + n] = v + bias[n];
                    }
                }
            }
        }
    }
}

// ---------------------------------------------------------------------------
// Fused preamble: blocks [0, H*S) do softmax rows -> g_Ph; the rest do
// grid-stride fp32->fp16 conversion (hidden, v_w, out_w).
// Q path cancels: softmax is shift-invariant along the last axis.
// ---------------------------------------------------------------------------
#define CVT_BLOCKS 2960
__global__ __launch_bounds__(256)
void preamble(const float* __restrict__ sbias,
              const float* __restrict__ hid,
              const float* __restrict__ vw,
              const float* __restrict__ ow)
{
    const int tid = threadIdx.x;
    if (blockIdx.x < H_ * S_) {
        const int row = blockIdx.x;
        const float* __restrict__ src = sbias + (size_t)row * S_;
        half* __restrict__ dh = g_Ph + (size_t)row * SP;

        __shared__ float shm[8], shs[8];

        float v0 = (tid       < S_) ? src[tid]       : -3.0e38f;
        float v1 = (tid + 256 < S_) ? src[tid + 256] : -3.0e38f;
        float v2 = (tid + 512 < S_) ? src[tid + 512] : -3.0e38f;

        float mx = fmaxf(v0, fmaxf(v1, v2));
#pragma unroll
        for (int o = 16; o > 0; o >>= 1) mx = fmaxf(mx, __shfl_xor_sync(0xffffffffu, mx, o));
        if ((tid & 31) == 0) shm[tid >> 5] = mx;
        __syncthreads();
        mx = shm[0];
#pragma unroll
        for (int w = 1; w < 8; w++) mx = fmaxf(mx, shm[w]);

        float e0 = __expf(v0 - mx), e1 = __expf(v1 - mx), e2 = __expf(v2 - mx);
        float s = e0 + e1 + e2;
#pragma unroll
        for (int o = 16; o > 0; o >>= 1) s += __shfl_xor_sync(0xffffffffu, s, o);
        if ((tid & 31) == 0) shs[tid >> 5] = s;
        __syncthreads();
        s = shs[0];
#pragma unroll
        for (int w = 1; w < 8; w++) s += shs[w];
        const float inv = 1.0f / s;

#pragma unroll
        for (int q = 0; q < 3; q++) {
            const int c = tid + q * 256;
            if (c < SP) {
                const float pv = (c < S_) ? (q == 0 ? e0 : q == 1 ? e1 : e2) * inv : 0.f;
                dh[c] = __float2half_rn(pv);
            }
        }
    } else {
        const size_t NH = (size_t)M_ * E_;
        const size_t NW = (size_t)E_ * E_;
        const size_t total = NH + 2 * NW;
        const size_t stride = (size_t)CVT_BLOCKS * 256;
        size_t i = (size_t)(blockIdx.x - H_ * S_) * 256 + tid;
        for (; i < total; i += stride) {
            if (i < NH)            g_Ah[i]           = __float2half_rn(hid[i]);
            else if (i < NH + NW)  g_Wv[i - NH]      = __float2half_rn(vw[i - NH]);
            else                   g_Wo[i - NH - NW] = __float2half_rn(ow[i - NH - NW]);
        }
    }
}

// ---------------------------------------------------------------------------
extern "C" void kernel_launch(void* const* d_in, const int* in_sizes, int n_in,
                              void* d_out, int out_size)
{
    const float* hidden = (const float*)d_in[0];
    const float* v_w    = (const float*)d_in[3];
    const float* v_b    = (const float*)d_in[4];
    const float* out_w  = (const float*)d_in[5];
    const float* out_b  = (const float*)d_in[6];
    const float* s_bias = (const float*)d_in[8];
    float* out = (float*)d_out;

    cudaFuncSetAttribute(gemm_hmma<0>, cudaFuncAttributeMaxDynamicSharedMemorySize, SMEM_SZ);
    cudaFuncSetAttribute(gemm_hmma<1>, cudaFuncAttributeMaxDynamicSharedMemorySize, SMEM_SZ);
    cudaFuncSetAttribute(gemm_hmma<2>, cudaFuncAttributeMaxDynamicSharedMemorySize, SMEM_SZ);

    preamble<<<H_ * S_ + CVT_BLOCKS, 256>>>(s_bias, hidden, v_w, out_w);

    const int MB = (M_ + BM - 1) / BM;                 // 145
    gemm_hmma<0><<<dim3(8, MB),     256, SMEM_SZ>>>(v_b, nullptr);     // V proj
    gemm_hmma<1><<<dim3(8, 10, 16), 256, SMEM_SZ>>>(nullptr, nullptr); // P @ V
    gemm_hmma<2><<<dim3(8, MB),     256, SMEM_SZ>>>(out_b, out);       // out proj
}

// round 11
// speedup vs baseline: 1.0471x; 1.0471x over previous
#include <cuda_runtime.h>
#include <cuda_fp16.h>
#include <cstdint>

#define B_ 16
#define S_ 577
#define SP 640               // padded seq (K padding for GEMM2)
#define E_ 1024
#define H_ 16
#define D_ 64
#define M_ (B_ * S_)         // 9232

// ---------------- scratch (static device globals, zero-init at load) -------
__device__ half g_Ah[(size_t)M_ * E_];                   // hidden fp16
__device__ half g_Wv[(size_t)E_ * E_];                   // v_w fp16
__device__ half g_Wo[(size_t)E_ * E_];                   // out_w fp16
__device__ half g_Vh[(size_t)H_ * E_ * SP];              // V^T [h][(b,d)][s] (pad=0)
__device__ half g_Ph[(size_t)H_ * S_ * SP];              // softmax(P) (pad=0)
__device__ half g_Oh[(size_t)M_ * E_];                   // attn out fp16

// ---------------- PTX helpers (portable sm_80-level) ------------------------
__device__ __forceinline__ uint32_t smem_u32(const void* p) {
    uint32_t a;
    asm("{ .reg .u64 t; cvta.to.shared.u64 t, %1; cvt.u32.u64 %0, t; }" : "=r"(a) : "l"(p));
    return a;
}
__device__ __forceinline__ void cp16(uint32_t dst, const void* src) {
    asm volatile("cp.async.cg.shared.global [%0], [%1], 16;" :: "r"(dst), "l"(src));
}
#define CP_COMMIT() asm volatile("cp.async.commit_group;" ::: "memory")
#define CP_WAIT2()  asm volatile("cp.async.wait_group 2;" ::: "memory")

__device__ __forceinline__ void ldsm4(uint32_t* r, uint32_t addr) {
    asm volatile("ldmatrix.sync.aligned.m8n8.x4.shared.b16 {%0,%1,%2,%3}, [%4];"
                 : "=r"(r[0]), "=r"(r[1]), "=r"(r[2]), "=r"(r[3]) : "r"(addr));
}
__device__ __forceinline__ void ldsm2(uint32_t* r, uint32_t addr) {
    asm volatile("ldmatrix.sync.aligned.m8n8.x2.shared.b16 {%0,%1}, [%2];"
                 : "=r"(r[0]), "=r"(r[1]) : "r"(addr));
}
__device__ __forceinline__ void mma_f16(float* c, const uint32_t* a, const uint32_t* b) {
    asm volatile("mma.sync.aligned.m16n8k16.row.col.f32.f16.f16.f32 "
                 "{%0,%1,%2,%3}, {%4,%5,%6,%7}, {%8,%9}, {%0,%1,%2,%3};"
                 : "+f"(c[0]), "+f"(c[1]), "+f"(c[2]), "+f"(c[3])
                 : "r"(a[0]), "r"(a[1]), "r"(a[2]), "r"(a[3]), "r"(b[0]), "r"(b[1]));
}

// ---------------- tiling ----------------------------------------------------
// SMEM-crossbar model (R9): tensor util ~ FLOP per LDSM byte.
// MODE 0/2: CTA 128x256, warp tile 64x64, 1 CTA/SM, NSTAGE=4 ->
//           single __syncthreads per k-iter, prefetch distance NSTG-1 = 3
//           (buffer (kt+3)%4 is never the one read in iteration kt — the
//           R10 NaN was prefetching kt+4 ≡ kt mod 4, racing the readers).
// MODE 1:   round-8 winner: CTA 64x128, warp 32x32, 3 CTA/SM, NSTAGE=3,
//           two syncs (prefetch writes the buffer just read).
// Row = 8 x 16B chunks, physical chunk = c ^ (row&7): conflict-free ldmatrix.
#define KBLK 64

__device__ __forceinline__ uint32_t swz(int row, int c) {
    return (uint32_t)(row * 128 + ((c ^ (row & 7)) << 4));
}

template <int MODE> struct Cfg {
    static constexpr int BM = (MODE == 1) ? 64 : 128;
    static constexpr int BN = (MODE == 1) ? 128 : 256;
    static constexpr int MT = BM / 32;           // m16 frags per warp (2 / 4)
    static constexpr int NT = BN / 32;           // n8  frags per warp (4 / 8)
    static constexpr int WMR = BM / 2;           // warp m-rows
    static constexpr int WNC = BN / 4;           // warp n-cols
    static constexpr int A_BYTES = BM * 128;
    static constexpr int STAGE = A_BYTES + BN * 128;
    static constexpr int NSTG = (MODE == 1) ? 3 : 4;
    static constexpr int SMEM = NSTG * STAGE;    // 73728 / 196608
    static constexpr int OCC = (MODE == 1) ? 3 : 1;
    static constexpr int NCHUNK = (BM + BN) * 8 / 256;   // 6 / 12
};

// ---------------------------------------------------------------------------
// fp16 HMMA GEMM, NT: C[m,n] = sum_k A[m,k]*B[n,k]
// MODE 0: V-proj   A=g_Ah, B=g_Wv, K=1024 -> g_Vh (V^T scatter, +v_b)
// MODE 1: P@V      A=g_Ph, B=g_Vh, K=640  -> g_Oh
// MODE 2: out-proj A=g_Oh, B=g_Wo, K=1024 -> d_out fp32 (+out_b)
// ---------------------------------------------------------------------------
template <int MODE>
__global__ __launch_bounds__(256, Cfg<MODE>::OCC)
void gemm_hmma(const float* __restrict__ bias, float* __restrict__ outp)
{
    using C = Cfg<MODE>;
    extern __shared__ __align__(1024) char smem[];
    const uint32_t sb = smem_u32(smem);
    const int tid  = threadIdx.x;
    const int wid  = tid >> 5, lane = tid & 31;
    const int wm   = wid & 1, wn = wid >> 1;      // warp grid 2m x 4n
    const int gid  = lane >> 2, tig = lane & 3;

    const half *Ah, *Bh;
    int Mrows, pitch, kiter;
    if (MODE == 0) {
        Ah = g_Ah; Bh = g_Wv;
        Mrows = M_; pitch = E_; kiter = E_ / KBLK;
    } else if (MODE == 1) {
        const size_t ho = (size_t)blockIdx.z;
        Ah = g_Ph + ho * S_ * SP;
        Bh = g_Vh + ho * E_ * SP;
        Mrows = S_; pitch = SP; kiter = SP / KBLK;
    } else {
        Ah = g_Oh; Bh = g_Wo;
        Mrows = M_; pitch = E_; kiter = E_ / KBLK;
    }
    const int tm0 = blockIdx.y * C::BM, tn0 = blockIdx.x * C::BN;

    auto do_load = [&](int kt) {
        if (kt < kiter) {
            const uint32_t sbase = sb + (uint32_t)(kt % C::NSTG) * C::STAGE;
            const int koff = kt * KBLK;
#pragma unroll
            for (int p = 0; p < C::NCHUNK; p++) {
                const int id = p * 256 + tid;
                if (id < C::BM * 8) {              // A chunk
                    const int row = id >> 3, c = id & 7;
                    int grow = tm0 + row;
                    if (grow >= Mrows) grow = 0;   // clamp: never stored
                    cp16(sbase + swz(row, c),
                         Ah + (size_t)grow * pitch + koff + c * 8);
                } else {                           // B chunk (N=1024 exact)
                    const int idb = id - C::BM * 8;
                    const int row = idb >> 3, c = idb & 7;
                    cp16(sbase + (uint32_t)C::A_BYTES + swz(row, c),
                         Bh + (size_t)(tn0 + row) * pitch + koff + c * 8);
                }
            }
        }
        CP_COMMIT();
    };

    float acc[C::MT][C::NT][4];
#pragma unroll
    for (int i = 0; i < C::MT; i++)
#pragma unroll
        for (int j = 0; j < C::NT; j++)
#pragma unroll
            for (int q = 0; q < 4; q++) acc[i][j][q] = 0.f;

    do_load(0); do_load(1); do_load(2);

    for (int kt = 0; kt < kiter; kt++) {
        CP_WAIT2();
        __syncthreads();
        const uint32_t Ab = sb + (uint32_t)(kt % C::NSTG) * C::STAGE;
        const uint32_t Bb = Ab + C::A_BYTES;

#pragma unroll
        for (int ks = 0; ks < 4; ks++) {           // 4 x k16 slices per k64
            uint32_t bf[C::NT][2];
#pragma unroll
            for (int nt = 0; nt < C::NT; nt++) {
                const int nr = wn * C::WNC + nt * 8 + (lane & 7);
                const int c  = ks * 2 + ((lane >> 3) & 1);
                ldsm2(bf[nt], Bb + swz(nr, c));
            }
#pragma unroll
            for (int mt = 0; mt < C::MT; mt++) {
                uint32_t ah[4];
                {
                    const int mr = wm * C::WMR + mt * 16 + (lane & 15);
                    const int kh = lane >> 4;
                    ldsm4(ah, Ab + swz(mr, ks * 2 + kh));
                }
#pragma unroll
                for (int nt = 0; nt < C::NT; nt++)
                    mma_f16(acc[mt][nt], ah, bf[nt]);
            }
        }
        if (C::NSTG == 3) __syncthreads();  // 3-stage: prefetch hits read buf
        do_load(kt + 3);                    // dist = NSTG-1 (4-stg) / NSTG (3-stg)
    }

    // ---------------- epilogue ----------------------------------------------
#pragma unroll
    for (int mt = 0; mt < C::MT; mt++) {
#pragma unroll
        for (int half_ = 0; half_ < 2; half_++) {
            const int m = tm0 + wm * C::WMR + mt * 16 + gid + half_ * 8;
            if (m >= Mrows) continue;
            int bb = 0, s = 0;
            if (MODE == 0) { bb = m / S_; s = m - bb * S_; }
#pragma unroll
            for (int nt = 0; nt < C::NT; nt++) {
                const int n0 = tn0 + wn * C::WNC + nt * 8 + tig * 2;
#pragma unroll
                for (int j = 0; j < 2; j++) {
                    const int n = n0 + j;
                    float v = acc[mt][nt][half_ * 2 + j];
                    if (MODE == 0) {
                        v += bias[n];
                        const size_t a = ((size_t)(n >> 6) * (B_ * D_)
                                          + (size_t)bb * D_ + (n & 63)) * SP + s;
                        g_Vh[a] = __float2half_rn(v);
                    } else if (MODE == 1) {
                        const size_t a = ((size_t)(n >> 6) * S_ + m) * E_
                                         + (size_t)blockIdx.z * D_ + (n & 63);
                        g_Oh[a] = __float2half_rn(v);
                    } else {
                        outp[(size_t)m * E_ + n] = v + bias[n];
                    }
                }
            }
        }
    }
}

// ---------------------------------------------------------------------------
// Fused preamble: blocks [0, H*S) do softmax rows -> g_Ph; the rest do
// grid-stride fp32->fp16 conversion (hidden, v_w, out_w).
// Q path cancels: softmax is shift-invariant along the last axis.
// ---------------------------------------------------------------------------
#define CVT_BLOCKS 2960
__global__ __launch_bounds__(256)
void preamble(const float* __restrict__ sbias,
              const float* __restrict__ hid,
              const float* __restrict__ vw,
              const float* __restrict__ ow)
{
    const int tid = threadIdx.x;
    if (blockIdx.x < H_ * S_) {
        const int row = blockIdx.x;
        const float* __restrict__ src = sbias + (size_t)row * S_;
        half* __restrict__ dh = g_Ph + (size_t)row * SP;

        __shared__ float shm[8], shs[8];

        float v0 = (tid       < S_) ? src[tid]       : -3.0e38f;
        float v1 = (tid + 256 < S_) ? src[tid + 256] : -3.0e38f;
        float v2 = (tid + 512 < S_) ? src[tid + 512] : -3.0e38f;

        float mx = fmaxf(v0, fmaxf(v1, v2));
#pragma unroll
        for (int o = 16; o > 0; o >>= 1) mx = fmaxf(mx, __shfl_xor_sync(0xffffffffu, mx, o));
        if ((tid & 31) == 0) shm[tid >> 5] = mx;
        __syncthreads();
        mx = shm[0];
#pragma unroll
        for (int w = 1; w < 8; w++) mx = fmaxf(mx, shm[w]);

        float e0 = __expf(v0 - mx), e1 = __expf(v1 - mx), e2 = __expf(v2 - mx);
        float s = e0 + e1 + e2;
#pragma unroll
        for (int o = 16; o > 0; o >>= 1) s += __shfl_xor_sync(0xffffffffu, s, o);
        if ((tid & 31) == 0) shs[tid >> 5] = s;
        __syncthreads();
        s = shs[0];
#pragma unroll
        for (int w = 1; w < 8; w++) s += shs[w];
        const float inv = 1.0f / s;

#pragma unroll
        for (int q = 0; q < 3; q++) {
            const int c = tid + q * 256;
            if (c < SP) {
                const float pv = (c < S_) ? (q == 0 ? e0 : q == 1 ? e1 : e2) * inv : 0.f;
                dh[c] = __float2half_rn(pv);
            }
        }
    } else {
        const size_t NH = (size_t)M_ * E_;
        const size_t NW = (size_t)E_ * E_;
        const size_t total = NH + 2 * NW;
        const size_t stride = (size_t)CVT_BLOCKS * 256;
        size_t i = (size_t)(blockIdx.x - H_ * S_) * 256 + tid;
        for (; i < total; i += stride) {
            if (i < NH)            g_Ah[i]           = __float2half_rn(hid[i]);
            else if (i < NH + NW)  g_Wv[i - NH]      = __float2half_rn(vw[i - NH]);
            else                   g_Wo[i - NH - NW] = __float2half_rn(ow[i - NH - NW]);
        }
    }
}

// ---------------------------------------------------------------------------
extern "C" void kernel_launch(void* const* d_in, const int* in_sizes, int n_in,
                              void* d_out, int out_size)
{
    const float* hidden = (const float*)d_in[0];
    const float* v_w    = (const float*)d_in[3];
    const float* v_b    = (const float*)d_in[4];
    const float* out_w  = (const float*)d_in[5];
    const float* out_b  = (const float*)d_in[6];
    const float* s_bias = (const float*)d_in[8];
    float* out = (float*)d_out;

    cudaFuncSetAttribute(gemm_hmma<0>, cudaFuncAttributeMaxDynamicSharedMemorySize, Cfg<0>::SMEM);
    cudaFuncSetAttribute(gemm_hmma<1>, cudaFuncAttributeMaxDynamicSharedMemorySize, Cfg<1>::SMEM);
    cudaFuncSetAttribute(gemm_hmma<2>, cudaFuncAttributeMaxDynamicSharedMemorySize, Cfg<2>::SMEM);

    preamble<<<H_ * S_ + CVT_BLOCKS, 256>>>(s_bias, hidden, v_w, out_w);

    gemm_hmma<0><<<dim3(4, 73),     256, Cfg<0>::SMEM>>>(v_b, nullptr);     // V proj
    gemm_hmma<1><<<dim3(8, 10, 16), 256, Cfg<1>::SMEM>>>(nullptr, nullptr); // P @ V
    gemm_hmma<2><<<dim3(4, 73),     256, Cfg<2>::SMEM>>>(out_b, out);       // out proj
}

// round 12
// speedup vs baseline: 1.1442x; 1.0927x over previous
#include <cuda_runtime.h>
#include <cuda_fp16.h>
#include <cstdint>

#define B_ 16
#define S_ 577
#define SP 640               // padded seq (K padding for GEMM2)
#define E_ 1024
#define H_ 16
#define D_ 64
#define M_ (B_ * S_)         // 9232

// ---------------- scratch (static device globals, zero-init at load) -------
__device__ half g_Ah[(size_t)M_ * E_];                   // hidden fp16
__device__ half g_Wv[(size_t)E_ * E_];                   // v_w fp16
__device__ half g_Wo[(size_t)E_ * E_];                   // out_w fp16
__device__ half g_Vh[(size_t)H_ * E_ * SP];              // V^T [h][(b,d)][s] (pad=0)
__device__ half g_Ph[(size_t)H_ * S_ * SP];              // softmax(P) (pad=0)
__device__ half g_Oh[(size_t)M_ * E_];                   // attn out fp16

// ---------------- PTX helpers (portable sm_80-level) ------------------------
__device__ __forceinline__ uint32_t smem_u32(const void* p) {
    uint32_t a;
    asm("{ .reg .u64 t; cvta.to.shared.u64 t, %1; cvt.u32.u64 %0, t; }" : "=r"(a) : "l"(p));
    return a;
}
__device__ __forceinline__ void cp16(uint32_t dst, const void* src) {
    asm volatile("cp.async.cg.shared.global [%0], [%1], 16;" :: "r"(dst), "l"(src));
}
#define CP_COMMIT() asm volatile("cp.async.commit_group;" ::: "memory")
template <int N>
__device__ __forceinline__ void cp_wait() {
    asm volatile("cp.async.wait_group %0;" :: "n"(N) : "memory");
}

__device__ __forceinline__ void ldsm4(uint32_t* r, uint32_t addr) {
    asm volatile("ldmatrix.sync.aligned.m8n8.x4.shared.b16 {%0,%1,%2,%3}, [%4];"
                 : "=r"(r[0]), "=r"(r[1]), "=r"(r[2]), "=r"(r[3]) : "r"(addr));
}
__device__ __forceinline__ void ldsm2(uint32_t* r, uint32_t addr) {
    asm volatile("ldmatrix.sync.aligned.m8n8.x2.shared.b16 {%0,%1}, [%2];"
                 : "=r"(r[0]), "=r"(r[1]) : "r"(addr));
}
__device__ __forceinline__ void mma_f16(float* c, const uint32_t* a, const uint32_t* b) {
    asm volatile("mma.sync.aligned.m16n8k16.row.col.f32.f16.f16.f32 "
                 "{%0,%1,%2,%3}, {%4,%5,%6,%7}, {%8,%9}, {%0,%1,%2,%3};"
                 : "+f"(c[0]), "+f"(c[1]), "+f"(c[2]), "+f"(c[3])
                 : "r"(a[0]), "r"(a[1]), "r"(a[2]), "r"(a[3]), "r"(b[0]), "r"(b[1]));
}

// ---------------- tiling ----------------------------------------------------
// ~52% tensor is the measured mma.sync plateau (R7/R8/R11): RF capacity forbids
// simultaneously relieving the SMEM crossbar (big warp tiles) and hiding
// latency (many warps). Use the best measured configs (R8) and trim overhead:
// MODE 0/2: CTA 128x128, warp 64x32, 2 CTA/SM, NSTAGE=3, SINGLE sync/iter
//           (prefetch dist 2 -> buffer (kt+2)%3 == (kt-1)%3, readers done at
//            the top-of-loop barrier; cp.async.wait_group 1 at top).
// MODE 1:   CTA 64x128, warp 32x32, 3 CTA/SM, NSTAGE=3, two syncs (R8 exact).
// Row = 8 x 16B chunks, physical chunk = c ^ (row&7): conflict-free ldmatrix.
#define KBLK 64

__device__ __forceinline__ uint32_t swz(int row, int c) {
    return (uint32_t)(row * 128 + ((c ^ (row & 7)) << 4));
}

template <int MODE> struct Cfg {
    static constexpr int BM = (MODE == 1) ? 64 : 128;
    static constexpr int BN = 128;
    static constexpr int MT = BM / 32;           // m16 frags per warp (2 / 4)
    static constexpr int NT = 4;                 // n8 frags per warp
    static constexpr int WMR = BM / 2;           // warp m-rows
    static constexpr int A_BYTES = BM * 128;
    static constexpr int STAGE = A_BYTES + BN * 128;
    static constexpr int SMEM = 3 * STAGE;       // 73728 / 98304
    static constexpr int OCC = (MODE == 1) ? 3 : 2;
    static constexpr int NCHUNK = (BM + BN) * 8 / 256;   // 6 / 8
    static constexpr bool ONESYNC = (MODE != 1);
};

// ---------------------------------------------------------------------------
// fp16 HMMA GEMM, NT: C[m,n] = sum_k A[m,k]*B[n,k]
// MODE 0: V-proj   A=g_Ah, B=g_Wv, K=1024 -> g_Vh (V^T scatter, +v_b)
// MODE 1: P@V      A=g_Ph, B=g_Vh, K=640  -> g_Oh
// MODE 2: out-proj A=g_Oh, B=g_Wo, K=1024 -> d_out fp32 (+out_b)
// ---------------------------------------------------------------------------
template <int MODE>
__global__ __launch_bounds__(256, Cfg<MODE>::OCC)
void gemm_hmma(const float* __restrict__ bias, float* __restrict__ outp)
{
    using C = Cfg<MODE>;
    extern __shared__ __align__(1024) char smem[];
    const uint32_t sb = smem_u32(smem);
    const int tid  = threadIdx.x;
    const int wid  = tid >> 5, lane = tid & 31;
    const int wm   = wid & 1, wn = wid >> 1;      // warp grid 2m x 4n
    const int gid  = lane >> 2, tig = lane & 3;

    const half *Ah, *Bh;
    int Mrows, pitch, kiter;
    if (MODE == 0) {
        Ah = g_Ah; Bh = g_Wv;
        Mrows = M_; pitch = E_; kiter = E_ / KBLK;
    } else if (MODE == 1) {
        const size_t ho = (size_t)blockIdx.z;
        Ah = g_Ph + ho * S_ * SP;
        Bh = g_Vh + ho * E_ * SP;
        Mrows = S_; pitch = SP; kiter = SP / KBLK;
    } else {
        Ah = g_Oh; Bh = g_Wo;
        Mrows = M_; pitch = E_; kiter = E_ / KBLK;
    }
    const int tm0 = blockIdx.y * C::BM, tn0 = blockIdx.x * C::BN;

    auto do_load = [&](int kt) {
        if (kt < kiter) {
            const uint32_t sbase = sb + (uint32_t)(kt % 3) * C::STAGE;
            const int koff = kt * KBLK;
#pragma unroll
            for (int p = 0; p < C::NCHUNK; p++) {
                const int id = p * 256 + tid;
                if (id < C::BM * 8) {              // A chunk
                    const int row = id >> 3, c = id & 7;
                    int grow = tm0 + row;
                    if (grow >= Mrows) grow = 0;   // clamp: never stored
                    cp16(sbase + swz(row, c),
                         Ah + (size_t)grow * pitch + koff + c * 8);
                } else {                           // B chunk (N=1024 exact)
                    const int idb = id - C::BM * 8;
                    const int row = idb >> 3, c = idb & 7;
                    cp16(sbase + (uint32_t)C::A_BYTES + swz(row, c),
                         Bh + (size_t)(tn0 + row) * pitch + koff + c * 8);
                }
            }
        }
        CP_COMMIT();
    };

    float acc[C::MT][C::NT][4];
#pragma unroll
    for (int i = 0; i < C::MT; i++)
#pragma unroll
        for (int j = 0; j < C::NT; j++)
#pragma unroll
            for (int q = 0; q < 4; q++) acc[i][j][q] = 0.f;

    do_load(0); do_load(1);
    if (!C::ONESYNC) do_load(2);

    for (int kt = 0; kt < kiter; kt++) {
        if (C::ONESYNC) cp_wait<1>(); else cp_wait<2>();
        __syncthreads();
        if (C::ONESYNC) do_load(kt + 2);           // (kt+2)%3==(kt-1)%3: done
        const uint32_t Ab = sb + (uint32_t)(kt % 3) * C::STAGE;
        const uint32_t Bb = Ab + C::A_BYTES;

#pragma unroll
        for (int ks = 0; ks < 4; ks++) {           // 4 x k16 slices per k64
            uint32_t bf[C::NT][2];
#pragma unroll
            for (int nt = 0; nt < C::NT; nt++) {
                const int nr = wn * 32 + nt * 8 + (lane & 7);
                const int c  = ks * 2 + ((lane >> 3) & 1);
                ldsm2(bf[nt], Bb + swz(nr, c));
            }
#pragma unroll
            for (int mt = 0; mt < C::MT; mt++) {
                uint32_t ah[4];
                {
                    const int mr = wm * C::WMR + mt * 16 + (lane & 15);
                    const int kh = lane >> 4;
                    ldsm4(ah, Ab + swz(mr, ks * 2 + kh));
                }
#pragma unroll
                for (int nt = 0; nt < C::NT; nt++)
                    mma_f16(acc[mt][nt], ah, bf[nt]);
            }
        }
        if (!C::ONESYNC) {                         // R8 path: prefetch hits
            __syncthreads();                       // the buffer just read
            do_load(kt + 3);
        }
    }

    // ---------------- epilogue ----------------------------------------------
#pragma unroll
    for (int mt = 0; mt < C::MT; mt++) {
#pragma unroll
        for (int half_ = 0; half_ < 2; half_++) {
            const int m = tm0 + wm * C::WMR + mt * 16 + gid + half_ * 8;
            if (m >= Mrows) continue;
            int bb = 0, s = 0;
            if (MODE == 0) { bb = m / S_; s = m - bb * S_; }
#pragma unroll
            for (int nt = 0; nt < C::NT; nt++) {
                const int n0 = tn0 + wn * 32 + nt * 8 + tig * 2;
#pragma unroll
                for (int j = 0; j < 2; j++) {
                    const int n = n0 + j;
                    float v = acc[mt][nt][half_ * 2 + j];
                    if (MODE == 0) {
                        v += bias[n];
                        const size_t a = ((size_t)(n >> 6) * (B_ * D_)
                                          + (size_t)bb * D_ + (n & 63)) * SP + s;
                        g_Vh[a] = __float2half_rn(v);
                    } else if (MODE == 1) {
                        const size_t a = ((size_t)(n >> 6) * S_ + m) * E_
                                         + (size_t)blockIdx.z * D_ + (n & 63);
                        g_Oh[a] = __float2half_rn(v);
                    } else {
                        outp[(size_t)m * E_ + n] = v + bias[n];
                    }
                }
            }
        }
    }
}

// ---------------------------------------------------------------------------
// Fused preamble: blocks [0, H*S) do softmax rows -> g_Ph; the rest do
// float4-vectorized fp32->fp16 conversion (hidden, v_w, out_w).
// Q path cancels: softmax is shift-invariant along the last axis.
// ---------------------------------------------------------------------------
#define CVT_BLOCKS 2960
__device__ __forceinline__ void cvt4(half* dst, const float* src, size_t i4) {
    const float4 v = *(const float4*)(src + i4 * 4);
    __half2 lo = __floats2half2_rn(v.x, v.y);
    __half2 hi = __floats2half2_rn(v.z, v.w);
    uint2 o;
    o.x = *(uint32_t*)&lo;
    o.y = *(uint32_t*)&hi;
    *(uint2*)(dst + i4 * 4) = o;
}

__global__ __launch_bounds__(256)
void preamble(const float* __restrict__ sbias,
              const float* __restrict__ hid,
              const float* __restrict__ vw,
              const float* __restrict__ ow)
{
    const int tid = threadIdx.x;
    if (blockIdx.x < H_ * S_) {
        const int row = blockIdx.x;
        const float* __restrict__ src = sbias + (size_t)row * S_;
        half* __restrict__ dh = g_Ph + (size_t)row * SP;

        __shared__ float shm[8], shs[8];

        float v0 = (tid       < S_) ? src[tid]       : -3.0e38f;
        float v1 = (tid + 256 < S_) ? src[tid + 256] : -3.0e38f;
        float v2 = (tid + 512 < S_) ? src[tid + 512] : -3.0e38f;

        float mx = fmaxf(v0, fmaxf(v1, v2));
#pragma unroll
        for (int o = 16; o > 0; o >>= 1) mx = fmaxf(mx, __shfl_xor_sync(0xffffffffu, mx, o));
        if ((tid & 31) == 0) shm[tid >> 5] = mx;
        __syncthreads();
        mx = shm[0];
#pragma unroll
        for (int w = 1; w < 8; w++) mx = fmaxf(mx, shm[w]);

        float e0 = __expf(v0 - mx), e1 = __expf(v1 - mx), e2 = __expf(v2 - mx);
        float s = e0 + e1 + e2;
#pragma unroll
        for (int o = 16; o > 0; o >>= 1) s += __shfl_xor_sync(0xffffffffu, s, o);
        if ((tid & 31) == 0) shs[tid >> 5] = s;
        __syncthreads();
        s = shs[0];
#pragma unroll
        for (int w = 1; w < 8; w++) s += shs[w];
        const float inv = 1.0f / s;

#pragma unroll
        for (int q = 0; q < 3; q++) {
            const int c = tid + q * 256;
            if (c < SP) {
                const float pv = (c < S_) ? (q == 0 ? e0 : q == 1 ? e1 : e2) * inv : 0.f;
                dh[c] = __float2half_rn(pv);
            }
        }
    } else {
        // float4 conversions; all segment sizes divisible by 4
        const size_t NH4 = (size_t)M_ * E_ / 4;
        const size_t NW4 = (size_t)E_ * E_ / 4;
        const size_t total = NH4 + 2 * NW4;
        const size_t stride = (size_t)CVT_BLOCKS * 256;
        size_t i = (size_t)(blockIdx.x - H_ * S_) * 256 + tid;
        for (; i < total; i += stride) {
            if (i < NH4)            cvt4(g_Ah, hid, i);
            else if (i < NH4 + NW4) cvt4(g_Wv, vw, i - NH4);
            else                    cvt4(g_Wo, ow, i - NH4 - NW4);
        }
    }
}

// ---------------------------------------------------------------------------
extern "C" void kernel_launch(void* const* d_in, const int* in_sizes, int n_in,
                              void* d_out, int out_size)
{
    const float* hidden = (const float*)d_in[0];
    const float* v_w    = (const float*)d_in[3];
    const float* v_b    = (const float*)d_in[4];
    const float* out_w  = (const float*)d_in[5];
    const float* out_b  = (const float*)d_in[6];
    const float* s_bias = (const float*)d_in[8];
    float* out = (float*)d_out;

    cudaFuncSetAttribute(gemm_hmma<0>, cudaFuncAttributeMaxDynamicSharedMemorySize, Cfg<0>::SMEM);
    cudaFuncSetAttribute(gemm_hmma<1>, cudaFuncAttributeMaxDynamicSharedMemorySize, Cfg<1>::SMEM);
    cudaFuncSetAttribute(gemm_hmma<2>, cudaFuncAttributeMaxDynamicSharedMemorySize, Cfg<2>::SMEM);

    preamble<<<H_ * S_ + CVT_BLOCKS, 256>>>(s_bias, hidden, v_w, out_w);

    gemm_hmma<0><<<dim3(8, 73),     256, Cfg<0>::SMEM>>>(v_b, nullptr);     // V proj
    gemm_hmma<1><<<dim3(8, 10, 16), 256, Cfg<1>::SMEM>>>(nullptr, nullptr); // P @ V
    gemm_hmma<2><<<dim3(8, 73),     256, Cfg<2>::SMEM>>>(out_b, out);       // out proj
}

// round 13
// speedup vs baseline: 1.1781x; 1.0296x over previous
#include <cuda_runtime.h>
#include <cuda_fp16.h>
#include <cstdint>

#define B_ 16
#define S_ 577
#define SP 640               // padded seq (K padding for GEMM2)
#define E_ 1024
#define H_ 16
#define D_ 64
#define M_ (B_ * S_)         // 9232

// ---------------- scratch (static device globals, zero-init at load) -------
__device__ half g_Ah[(size_t)M_ * E_];                   // hidden fp16
__device__ half g_Wv[(size_t)E_ * E_];                   // v_w fp16
__device__ half g_Wo[(size_t)E_ * E_];                   // out_w fp16
__device__ half g_Vh[(size_t)H_ * E_ * SP];              // V^T [h][(b,d)][s] (pad=0)
__device__ half g_Ph[(size_t)H_ * S_ * SP];              // softmax(P) (pad=0)
__device__ half g_Oh[(size_t)M_ * E_];                   // attn out fp16

// ---------------- PTX helpers (portable sm_80-level) ------------------------
__device__ __forceinline__ uint32_t smem_u32(const void* p) {
    uint32_t a;
    asm("{ .reg .u64 t; cvta.to.shared.u64 t, %1; cvt.u32.u64 %0, t; }" : "=r"(a) : "l"(p));
    return a;
}
__device__ __forceinline__ void cp16(uint32_t dst, const void* src) {
    asm volatile("cp.async.cg.shared.global [%0], [%1], 16;" :: "r"(dst), "l"(src));
}
#define CP_COMMIT() asm volatile("cp.async.commit_group;" ::: "memory")
template <int N>
__device__ __forceinline__ void cp_wait() {
    asm volatile("cp.async.wait_group %0;" :: "n"(N) : "memory");
}

__device__ __forceinline__ void ldsm4(uint32_t* r, uint32_t addr) {
    asm volatile("ldmatrix.sync.aligned.m8n8.x4.shared.b16 {%0,%1,%2,%3}, [%4];"
                 : "=r"(r[0]), "=r"(r[1]), "=r"(r[2]), "=r"(r[3]) : "r"(addr));
}
__device__ __forceinline__ void ldsm2(uint32_t* r, uint32_t addr) {
    asm volatile("ldmatrix.sync.aligned.m8n8.x2.shared.b16 {%0,%1}, [%2];"
                 : "=r"(r[0]), "=r"(r[1]) : "r"(addr));
}
__device__ __forceinline__ void mma_f16(float* c, const uint32_t* a, const uint32_t* b) {
    asm volatile("mma.sync.aligned.m16n8k16.row.col.f32.f16.f16.f32 "
                 "{%0,%1,%2,%3}, {%4,%5,%6,%7}, {%8,%9}, {%0,%1,%2,%3};"
                 : "+f"(c[0]), "+f"(c[1]), "+f"(c[2]), "+f"(c[3])
                 : "r"(a[0]), "r"(a[1]), "r"(a[2]), "r"(a[3]), "r"(b[0]), "r"(b[1]));
}

// ---------------- tiling ----------------------------------------------------
// Crossbar model (validated R12): LDSM B/MAC = 2(WM+WN)/(WM*WN); budget =
// 128 B/cyc / 1024 MAC/cyc = 0.125. 64x32 warp tile + stores = 0.125 ->
// saturated at tensor ~53%. Fix: 64x64 warp tiles (0.063 + 0.023 stores =
// 0.086) AND 2 co-resident CTAs (R11 failed with 1 CTA: barrier idles SM).
// MODE 0/2: CTA 128x128, 128 threads = 4 warps (2x2 grid of 64x64), 2 CTA/SM,
//           3 stages, single sync/iter (prefetch dist 2 — verified R12).
// MODE 1:   R8 winner: CTA 64x128, 256 thr, warp 32x32, 3 CTA/SM, two syncs.
// Row = 8 x 16B chunks, physical chunk = c ^ (row&7): conflict-free ldmatrix.
#define KBLK 64

__device__ __forceinline__ uint32_t swz(int row, int c) {
    return (uint32_t)(row * 128 + ((c ^ (row & 7)) << 4));
}

template <int MODE> struct Cfg {
    static constexpr int NTH = (MODE == 1) ? 256 : 128;
    static constexpr int BM  = (MODE == 1) ? 64 : 128;
    static constexpr int BN  = 128;
    static constexpr int WMR = (MODE == 1) ? 32 : 64;    // warp tile m
    static constexpr int WNC = (MODE == 1) ? 32 : 64;    // warp tile n
    static constexpr int MT  = WMR / 16;                 // 2 / 4
    static constexpr int NT  = WNC / 8;                  // 4 / 8
    static constexpr int A_BYTES = BM * 128;
    static constexpr int STAGE = A_BYTES + BN * 128;
    static constexpr int SMEM = 3 * STAGE;               // 73728 / 98304
    static constexpr int OCC = (MODE == 1) ? 3 : 2;
    static constexpr int NCHUNK = (BM + BN) * 8 / NTH;   // 6 / 16
    static constexpr bool ONESYNC = (MODE != 1);
};

// ---------------------------------------------------------------------------
// fp16 HMMA GEMM, NT: C[m,n] = sum_k A[m,k]*B[n,k]
// MODE 0: V-proj   A=g_Ah, B=g_Wv, K=1024 -> g_Vh (V^T scatter, +v_b)
// MODE 1: P@V      A=g_Ph, B=g_Vh, K=640  -> g_Oh
// MODE 2: out-proj A=g_Oh, B=g_Wo, K=1024 -> d_out fp32 (+out_b)
// ---------------------------------------------------------------------------
template <int MODE>
__global__ __launch_bounds__(Cfg<MODE>::NTH, Cfg<MODE>::OCC)
void gemm_hmma(const float* __restrict__ bias, float* __restrict__ outp)
{
    using C = Cfg<MODE>;
    extern __shared__ __align__(1024) char smem[];
    const uint32_t sb = smem_u32(smem);
    const int tid  = threadIdx.x;
    const int wid  = tid >> 5, lane = tid & 31;
    const int wm   = wid & 1, wn = wid >> 1;      // 2x2 (4 warps) / 2x4 (8)
    const int gid  = lane >> 2, tig = lane & 3;

    const half *Ah, *Bh;
    int Mrows, pitch, kiter;
    if (MODE == 0) {
        Ah = g_Ah; Bh = g_Wv;
        Mrows = M_; pitch = E_; kiter = E_ / KBLK;
    } else if (MODE == 1) {
        const size_t ho = (size_t)blockIdx.z;
        Ah = g_Ph + ho * S_ * SP;
        Bh = g_Vh + ho * E_ * SP;
        Mrows = S_; pitch = SP; kiter = SP / KBLK;
    } else {
        Ah = g_Oh; Bh = g_Wo;
        Mrows = M_; pitch = E_; kiter = E_ / KBLK;
    }
    const int tm0 = blockIdx.y * C::BM, tn0 = blockIdx.x * C::BN;

    auto do_load = [&](int kt) {
        if (kt < kiter) {
            const uint32_t sbase = sb + (uint32_t)(kt % 3) * C::STAGE;
            const int koff = kt * KBLK;
#pragma unroll
            for (int p = 0; p < C::NCHUNK; p++) {
                const int id = p * C::NTH + tid;
                if (id < C::BM * 8) {              // A chunk
                    const int row = id >> 3, c = id & 7;
                    int grow = tm0 + row;
                    if (grow >= Mrows) grow = 0;   // clamp: never stored
                    cp16(sbase + swz(row, c),
                         Ah + (size_t)grow * pitch + koff + c * 8);
                } else {                           // B chunk (N=1024 exact)
                    const int idb = id - C::BM * 8;
                    const int row = idb >> 3, c = idb & 7;
                    cp16(sbase + (uint32_t)C::A_BYTES + swz(row, c),
                         Bh + (size_t)(tn0 + row) * pitch + koff + c * 8);
                }
            }
        }
        CP_COMMIT();
    };

    float acc[C::MT][C::NT][4];
#pragma unroll
    for (int i = 0; i < C::MT; i++)
#pragma unroll
        for (int j = 0; j < C::NT; j++)
#pragma unroll
            for (int q = 0; q < 4; q++) acc[i][j][q] = 0.f;

    do_load(0); do_load(1);
    if (!C::ONESYNC) do_load(2);

    for (int kt = 0; kt < kiter; kt++) {
        if (C::ONESYNC) cp_wait<1>(); else cp_wait<2>();
        __syncthreads();
        if (C::ONESYNC) do_load(kt + 2);           // (kt+2)%3==(kt-1)%3: done
        const uint32_t Ab = sb + (uint32_t)(kt % 3) * C::STAGE;
        const uint32_t Bb = Ab + C::A_BYTES;

#pragma unroll
        for (int ks = 0; ks < 4; ks++) {           // 4 x k16 slices per k64
            uint32_t bf[C::NT][2];
#pragma unroll
            for (int nt = 0; nt < C::NT; nt++) {
                const int nr = wn * C::WNC + nt * 8 + (lane & 7);
                const int c  = ks * 2 + ((lane >> 3) & 1);
                ldsm2(bf[nt], Bb + swz(nr, c));
            }
#pragma unroll
            for (int mt = 0; mt < C::MT; mt++) {
                uint32_t ah[4];
                {
                    const int mr = wm * C::WMR + mt * 16 + (lane & 15);
                    const int kh = lane >> 4;
                    ldsm4(ah, Ab + swz(mr, ks * 2 + kh));
                }
#pragma unroll
                for (int nt = 0; nt < C::NT; nt++)
                    mma_f16(acc[mt][nt], ah, bf[nt]);
            }
        }
        if (!C::ONESYNC) {                         // R8 path: prefetch hits
            __syncthreads();                       // the buffer just read
            do_load(kt + 3);
        }
    }

    // ---------------- epilogue ----------------------------------------------
#pragma unroll
    for (int mt = 0; mt < C::MT; mt++) {
#pragma unroll
        for (int half_ = 0; half_ < 2; half_++) {
            const int m = tm0 + wm * C::WMR + mt * 16 + gid + half_ * 8;
            if (m >= Mrows) continue;
            int bb = 0, s = 0;
            if (MODE == 0) { bb = m / S_; s = m - bb * S_; }
#pragma unroll
            for (int nt = 0; nt < C::NT; nt++) {
                const int n0 = tn0 + wn * C::WNC + nt * 8 + tig * 2;
#pragma unroll
                for (int j = 0; j < 2; j++) {
                    const int n = n0 + j;
                    float v = acc[mt][nt][half_ * 2 + j];
                    if (MODE == 0) {
                        v += bias[n];
                        const size_t a = ((size_t)(n >> 6) * (B_ * D_)
                                          + (size_t)bb * D_ + (n & 63)) * SP + s;
                        g_Vh[a] = __float2half_rn(v);
                    } else if (MODE == 1) {
                        const size_t a = ((size_t)(n >> 6) * S_ + m) * E_
                                         + (size_t)blockIdx.z * D_ + (n & 63);
                        g_Oh[a] = __float2half_rn(v);
                    } else {
                        outp[(size_t)m * E_ + n] = v + bias[n];
                    }
                }
            }
        }
    }
}

// ---------------------------------------------------------------------------
// Fused preamble: blocks [0, H*S) do softmax rows -> g_Ph; the rest do
// float4-vectorized fp32->fp16 conversion (hidden, v_w, out_w).
// Q path cancels: softmax is shift-invariant along the last axis.
// ---------------------------------------------------------------------------
#define CVT_BLOCKS 2960
__device__ __forceinline__ void cvt4(half* dst, const float* src, size_t i4) {
    const float4 v = *(const float4*)(src + i4 * 4);
    __half2 lo = __floats2half2_rn(v.x, v.y);
    __half2 hi = __floats2half2_rn(v.z, v.w);
    uint2 o;
    o.x = *(uint32_t*)&lo;
    o.y = *(uint32_t*)&hi;
    *(uint2*)(dst + i4 * 4) = o;
}

__global__ __launch_bounds__(256)
void preamble(const float* __restrict__ sbias,
              const float* __restrict__ hid,
              const float* __restrict__ vw,
              const float* __restrict__ ow)
{
    const int tid = threadIdx.x;
    if (blockIdx.x < H_ * S_) {
        const int row = blockIdx.x;
        const float* __restrict__ src = sbias + (size_t)row * S_;
        half* __restrict__ dh = g_Ph + (size_t)row * SP;

        __shared__ float shm[8], shs[8];

        float v0 = (tid       < S_) ? src[tid]       : -3.0e38f;
        float v1 = (tid + 256 < S_) ? src[tid + 256] : -3.0e38f;
        float v2 = (tid + 512 < S_) ? src[tid + 512] : -3.0e38f;

        float mx = fmaxf(v0, fmaxf(v1, v2));
#pragma unroll
        for (int o = 16; o > 0; o >>= 1) mx = fmaxf(mx, __shfl_xor_sync(0xffffffffu, mx, o));
        if ((tid & 31) == 0) shm[tid >> 5] = mx;
        __syncthreads();
        mx = shm[0];
#pragma unroll
        for (int w = 1; w < 8; w++) mx = fmaxf(mx, shm[w]);

        float e0 = __expf(v0 - mx), e1 = __expf(v1 - mx), e2 = __expf(v2 - mx);
        float s = e0 + e1 + e2;
#pragma unroll
        for (int o = 16; o > 0; o >>= 1) s += __shfl_xor_sync(0xffffffffu, s, o);
        if ((tid & 31) == 0) shs[tid >> 5] = s;
        __syncthreads();
        s = shs[0];
#pragma unroll
        for (int w = 1; w < 8; w++) s += shs[w];
        const float inv = 1.0f / s;

#pragma unroll
        for (int q = 0; q < 3; q++) {
            const int c = tid + q * 256;
            if (c < SP) {
                const float pv = (c < S_) ? (q == 0 ? e0 : q == 1 ? e1 : e2) * inv : 0.f;
                dh[c] = __float2half_rn(pv);
            }
        }
    } else {
        // float4 conversions; all segment sizes divisible by 4
        const size_t NH4 = (size_t)M_ * E_ / 4;
        const size_t NW4 = (size_t)E_ * E_ / 4;
        const size_t total = NH4 + 2 * NW4;
        const size_t stride = (size_t)CVT_BLOCKS * 256;
        size_t i = (size_t)(blockIdx.x - H_ * S_) * 256 + tid;
        for (; i < total; i += stride) {
            if (i < NH4)            cvt4(g_Ah, hid, i);
            else if (i < NH4 + NW4) cvt4(g_Wv, vw, i - NH4);
            else                    cvt4(g_Wo, ow, i - NH4 - NW4);
        }
    }
}

// ---------------------------------------------------------------------------
extern "C" void kernel_launch(void* const* d_in, const int* in_sizes, int n_in,
                              void* d_out, int out_size)
{
    const float* hidden = (const float*)d_in[0];
    const float* v_w    = (const float*)d_in[3];
    const float* v_b    = (const float*)d_in[4];
    const float* out_w  = (const float*)d_in[5];
    const float* out_b  = (const float*)d_in[6];
    const float* s_bias = (const float*)d_in[8];
    float* out = (float*)d_out;

    cudaFuncSetAttribute(gemm_hmma<0>, cudaFuncAttributeMaxDynamicSharedMemorySize, Cfg<0>::SMEM);
    cudaFuncSetAttribute(gemm_hmma<1>, cudaFuncAttributeMaxDynamicSharedMemorySize, Cfg<1>::SMEM);
    cudaFuncSetAttribute(gemm_hmma<2>, cudaFuncAttributeMaxDynamicSharedMemorySize, Cfg<2>::SMEM);

    preamble<<<H_ * S_ + CVT_BLOCKS, 256>>>(s_bias, hidden, v_w, out_w);

    gemm_hmma<0><<<dim3(8, 73),     Cfg<0>::NTH, Cfg<0>::SMEM>>>(v_b, nullptr);
    gemm_hmma<1><<<dim3(8, 10, 16), Cfg<1>::NTH, Cfg<1>::SMEM>>>(nullptr, nullptr);
    gemm_hmma<2><<<dim3(8, 73),     Cfg<2>::NTH, Cfg<2>::SMEM>>>(out_b, out);
}

// round 14
// speedup vs baseline: 1.3048x; 1.1076x over previous
#include <cuda_runtime.h>
#include <cuda_fp16.h>
#include <cstdint>

#define B_ 16
#define S_ 577
#define SP 640               // padded seq (K padding for GEMM2)
#define E_ 1024
#define H_ 16
#define D_ 64
#define M_ (B_ * S_)         // 9232

// ---------------- scratch (static device globals, zero-init at load) -------
__device__ half g_Ah[(size_t)M_ * E_];                   // hidden fp16
__device__ half g_Wv[(size_t)E_ * E_];                   // v_w fp16
__device__ half g_Wo[(size_t)E_ * E_];                   // out_w fp16
__device__ half g_Vh[(size_t)H_ * E_ * SP];              // V^T [h][(b,d)][s] (pad=0)
__device__ half g_Ph[(size_t)H_ * S_ * SP];              // softmax(P) (pad=0)
__device__ half g_Oh[(size_t)M_ * E_];                   // attn out fp16

// ---------------- PTX helpers (portable sm_80-level) ------------------------
__device__ __forceinline__ uint32_t smem_u32(const void* p) {
    uint32_t a;
    asm("{ .reg .u64 t; cvta.to.shared.u64 t, %1; cvt.u32.u64 %0, t; }" : "=r"(a) : "l"(p));
    return a;
}
__device__ __forceinline__ void cp16(uint32_t dst, const void* src) {
    asm volatile("cp.async.cg.shared.global [%0], [%1], 16;" :: "r"(dst), "l"(src));
}
#define CP_COMMIT() asm volatile("cp.async.commit_group;" ::: "memory")
template <int N>
__device__ __forceinline__ void cp_wait() {
    asm volatile("cp.async.wait_group %0;" :: "n"(N) : "memory");
}

__device__ __forceinline__ void ldsm4(uint32_t* r, uint32_t addr) {
    asm volatile("ldmatrix.sync.aligned.m8n8.x4.shared.b16 {%0,%1,%2,%3}, [%4];"
                 : "=r"(r[0]), "=r"(r[1]), "=r"(r[2]), "=r"(r[3]) : "r"(addr));
}
__device__ __forceinline__ void mma_f16(float* c, const uint32_t* a, const uint32_t* b) {
    asm volatile("mma.sync.aligned.m16n8k16.row.col.f32.f16.f16.f32 "
                 "{%0,%1,%2,%3}, {%4,%5,%6,%7}, {%8,%9}, {%0,%1,%2,%3};"
                 : "+f"(c[0]), "+f"(c[1]), "+f"(c[2]), "+f"(c[3])
                 : "r"(a[0]), "r"(a[1]), "r"(a[2]), "r"(a[3]), "r"(b[0]), "r"(b[1]));
}

// ---------------- tiling ----------------------------------------------------
// R13-verified configs; this round adds ldsm4 B-loads + vector epilogues.
// MODE 0/2: CTA 128x128, 128 thr = 4 warps of 64x64, 2 CTA/SM, 3 stages,
//           single sync/iter (prefetch dist 2).
// MODE 1:   CTA 64x128, 256 thr, warp 32x32, 3 CTA/SM, two syncs.
// Row = 8 x 16B chunks, physical chunk = c ^ (row&7): conflict-free ldmatrix.
#define KBLK 64

__device__ __forceinline__ uint32_t swz(int row, int c) {
    return (uint32_t)(row * 128 + ((c ^ (row & 7)) << 4));
}

template <int MODE> struct Cfg {
    static constexpr int NTH = (MODE == 1) ? 256 : 128;
    static constexpr int BM  = (MODE == 1) ? 64 : 128;
    static constexpr int BN  = 128;
    static constexpr int WMR = (MODE == 1) ? 32 : 64;    // warp tile m
    static constexpr int WNC = (MODE == 1) ? 32 : 64;    // warp tile n
    static constexpr int MT  = WMR / 16;                 // 2 / 4
    static constexpr int NT  = WNC / 8;                  // 4 / 8
    static constexpr int A_BYTES = BM * 128;
    static constexpr int STAGE = A_BYTES + BN * 128;
    static constexpr int SMEM = 3 * STAGE;               // 73728 / 98304
    static constexpr int OCC = (MODE == 1) ? 3 : 2;
    static constexpr int NCHUNK = (BM + BN) * 8 / NTH;   // 6 / 16
    static constexpr bool ONESYNC = (MODE != 1);
};

// ---------------------------------------------------------------------------
// fp16 HMMA GEMM, NT: C[m,n] = sum_k A[m,k]*B[n,k]
// MODE 0: V-proj   A=g_Ah, B=g_Wv, K=1024 -> g_Vh (V^T scatter, +v_b)
// MODE 1: P@V      A=g_Ph, B=g_Vh, K=640  -> g_Oh
// MODE 2: out-proj A=g_Oh, B=g_Wo, K=1024 -> d_out fp32 (+out_b)
// ---------------------------------------------------------------------------
template <int MODE>
__global__ __launch_bounds__(Cfg<MODE>::NTH, Cfg<MODE>::OCC)
void gemm_hmma(const float* __restrict__ bias, float* __restrict__ outp)
{
    using C = Cfg<MODE>;
    extern __shared__ __align__(1024) char smem[];
    const uint32_t sb = smem_u32(smem);
    const int tid  = threadIdx.x;
    const int wid  = tid >> 5, lane = tid & 31;
    const int wm   = wid & 1, wn = wid >> 1;      // 2x2 (4 warps) / 2x4 (8)
    const int gid  = lane >> 2, tig = lane & 3;

    const half *Ah, *Bh;
    int Mrows, pitch, kiter;
    if (MODE == 0) {
        Ah = g_Ah; Bh = g_Wv;
        Mrows = M_; pitch = E_; kiter = E_ / KBLK;
    } else if (MODE == 1) {
        const size_t ho = (size_t)blockIdx.z;
        Ah = g_Ph + ho * S_ * SP;
        Bh = g_Vh + ho * E_ * SP;
        Mrows = S_; pitch = SP; kiter = SP / KBLK;
    } else {
        Ah = g_Oh; Bh = g_Wo;
        Mrows = M_; pitch = E_; kiter = E_ / KBLK;
    }
    const int tm0 = blockIdx.y * C::BM, tn0 = blockIdx.x * C::BN;

    auto do_load = [&](int kt) {
        if (kt < kiter) {
            const uint32_t sbase = sb + (uint32_t)(kt % 3) * C::STAGE;
            const int koff = kt * KBLK;
#pragma unroll
            for (int p = 0; p < C::NCHUNK; p++) {
                const int id = p * C::NTH + tid;
                if (id < C::BM * 8) {              // A chunk
                    const int row = id >> 3, c = id & 7;
                    int grow = tm0 + row;
                    if (grow >= Mrows) grow = 0;   // clamp: never stored
                    cp16(sbase + swz(row, c),
                         Ah + (size_t)grow * pitch + koff + c * 8);
                } else {                           // B chunk (N=1024 exact)
                    const int idb = id - C::BM * 8;
                    const int row = idb >> 3, c = idb & 7;
                    cp16(sbase + (uint32_t)C::A_BYTES + swz(row, c),
                         Bh + (size_t)(tn0 + row) * pitch + koff + c * 8);
                }
            }
        }
        CP_COMMIT();
    };

    float acc[C::MT][C::NT][4];
#pragma unroll
    for (int i = 0; i < C::MT; i++)
#pragma unroll
        for (int j = 0; j < C::NT; j++)
#pragma unroll
            for (int q = 0; q < 4; q++) acc[i][j][q] = 0.f;

    do_load(0); do_load(1);
    if (!C::ONESYNC) do_load(2);

    for (int kt = 0; kt < kiter; kt++) {
        if (C::ONESYNC) cp_wait<1>(); else cp_wait<2>();
        __syncthreads();
        if (C::ONESYNC) do_load(kt + 2);           // (kt+2)%3==(kt-1)%3: done
        const uint32_t Ab = sb + (uint32_t)(kt % 3) * C::STAGE;
        const uint32_t Bb = Ab + C::A_BYTES;

#pragma unroll
        for (int ks = 0; ks < 4; ks++) {           // 4 x k16 slices per k64
            // B fragments via ldmatrix.x4: lanes 0-7 -> (nt,k0), 8-15 ->
            // (nt,k1), 16-23 -> (nt+1,k0), 24-31 -> (nt+1,k1)
            uint32_t bf[C::NT * 2];
#pragma unroll
            for (int ntp = 0; ntp < C::NT / 2; ntp++) {
                const int nr = wn * C::WNC + (ntp * 2 + ((lane >> 4) & 1)) * 8
                               + (lane & 7);
                const int c  = ks * 2 + ((lane >> 3) & 1);
                ldsm4(&bf[ntp * 4], Bb + swz(nr, c));
            }
#pragma unroll
            for (int mt = 0; mt < C::MT; mt++) {
                uint32_t ah[4];
                {
                    const int mr = wm * C::WMR + mt * 16 + (lane & 15);
                    const int kh = lane >> 4;
                    ldsm4(ah, Ab + swz(mr, ks * 2 + kh));
                }
#pragma unroll
                for (int nt = 0; nt < C::NT; nt++)
                    mma_f16(acc[mt][nt], ah, &bf[nt * 2]);
            }
        }
        if (!C::ONESYNC) {                         // R8 path: prefetch hits
            __syncthreads();                       // the buffer just read
            do_load(kt + 3);
        }
    }

    // ---------------- epilogue ----------------------------------------------
#pragma unroll
    for (int mt = 0; mt < C::MT; mt++) {
#pragma unroll
        for (int half_ = 0; half_ < 2; half_++) {
            const int m = tm0 + wm * C::WMR + mt * 16 + gid + half_ * 8;
            if (m >= Mrows) continue;
            int bb = 0, s = 0;
            if (MODE == 0) { bb = m / S_; s = m - bb * S_; }
#pragma unroll
            for (int nt = 0; nt < C::NT; nt++) {
                const int n0 = tn0 + wn * C::WNC + nt * 8 + tig * 2;
                const float v0 = acc[mt][nt][half_ * 2 + 0];
                const float v1 = acc[mt][nt][half_ * 2 + 1];
                if (MODE == 0) {
                    // scatter: n-neighbors are SP apart -> scalar stores
#pragma unroll
                    for (int j = 0; j < 2; j++) {
                        const int n = n0 + j;
                        const float v = (j ? v1 : v0) + bias[n];
                        const size_t a = ((size_t)(n >> 6) * (B_ * D_)
                                          + (size_t)bb * D_ + (n & 63)) * SP + s;
                        g_Vh[a] = __float2half_rn(v);
                    }
                } else if (MODE == 1) {
                    const size_t a = ((size_t)(n0 >> 6) * S_ + m) * E_
                                     + (size_t)blockIdx.z * D_ + (n0 & 63);
                    *(__half2*)(g_Oh + a) = __floats2half2_rn(v0, v1);
                } else {
                    float2 o;
                    o.x = v0 + bias[n0];
                    o.y = v1 + bias[n0 + 1];
                    *(float2*)(outp + (size_t)m * E_ + n0) = o;
                }
            }
        }
    }
}

// ---------------------------------------------------------------------------
// Fused preamble: blocks [0, H*S) do softmax rows -> g_Ph; the rest do
// float4-vectorized fp32->fp16 conversion (hidden, v_w, out_w).
// Q path cancels: softmax is shift-invariant along the last axis.
// ---------------------------------------------------------------------------
#define CVT_BLOCKS 2960
__device__ __forceinline__ void cvt4(half* dst, const float* src, size_t i4) {
    const float4 v = *(const float4*)(src + i4 * 4);
    __half2 lo = __floats2half2_rn(v.x, v.y);
    __half2 hi = __floats2half2_rn(v.z, v.w);
    uint2 o;
    o.x = *(uint32_t*)&lo;
    o.y = *(uint32_t*)&hi;
    *(uint2*)(dst + i4 * 4) = o;
}

__global__ __launch_bounds__(256)
void preamble(const float* __restrict__ sbias,
              const float* __restrict__ hid,
              const float* __restrict__ vw,
              const float* __restrict__ ow)
{
    const int tid = threadIdx.x;
    if (blockIdx.x < H_ * S_) {
        const int row = blockIdx.x;
        const float* __restrict__ src = sbias + (size_t)row * S_;
        half* __restrict__ dh = g_Ph + (size_t)row * SP;

        __shared__ float shm[8], shs[8];

        float v0 = (tid       < S_) ? src[tid]       : -3.0e38f;
        float v1 = (tid + 256 < S_) ? src[tid + 256] : -3.0e38f;
        float v2 = (tid + 512 < S_) ? src[tid + 512] : -3.0e38f;

        float mx = fmaxf(v0, fmaxf(v1, v2));
#pragma unroll
        for (int o = 16; o > 0; o >>= 1) mx = fmaxf(mx, __shfl_xor_sync(0xffffffffu, mx, o));
        if ((tid & 31) == 0) shm[tid >> 5] = mx;
        __syncthreads();
        mx = shm[0];
#pragma unroll
        for (int w = 1; w < 8; w++) mx = fmaxf(mx, shm[w]);

        float e0 = __expf(v0 - mx), e1 = __expf(v1 - mx), e2 = __expf(v2 - mx);
        float s = e0 + e1 + e2;
#pragma unroll
        for (int o = 16; o > 0; o >>= 1) s += __shfl_xor_sync(0xffffffffu, s, o);
        if ((tid & 31) == 0) shs[tid >> 5] = s;
        __syncthreads();
        s = shs[0];
#pragma unroll
        for (int w = 1; w < 8; w++) s += shs[w];
        const float inv = 1.0f / s;

#pragma unroll
        for (int q = 0; q < 3; q++) {
            const int c = tid + q * 256;
            if (c < SP) {
                const float pv = (c < S_) ? (q == 0 ? e0 : q == 1 ? e1 : e2) * inv : 0.f;
                dh[c] = __float2half_rn(pv);
            }
        }
    } else {
        // float4 conversions; all segment sizes divisible by 4
        const size_t NH4 = (size_t)M_ * E_ / 4;
        const size_t NW4 = (size_t)E_ * E_ / 4;
        const size_t total = NH4 + 2 * NW4;
        const size_t stride = (size_t)CVT_BLOCKS * 256;
        size_t i = (size_t)(blockIdx.x - H_ * S_) * 256 + tid;
        for (; i < total; i += stride) {
            if (i < NH4)            cvt4(g_Ah, hid, i);
            else if (i < NH4 + NW4) cvt4(g_Wv, vw, i - NH4);
            else                    cvt4(g_Wo, ow, i - NH4 - NW4);
        }
    }
}

// ---------------------------------------------------------------------------
extern "C" void kernel_launch(void* const* d_in, const int* in_sizes, int n_in,
                              void* d_out, int out_size)
{
    const float* hidden = (const float*)d_in[0];
    const float* v_w    = (const float*)d_in[3];
    const float* v_b    = (const float*)d_in[4];
    const float* out_w  = (const float*)d_in[5];
    const float* out_b  = (const float*)d_in[6];
    const float* s_bias = (const float*)d_in[8];
    float* out = (float*)d_out;

    cudaFuncSetAttribute(gemm_hmma<0>, cudaFuncAttributeMaxDynamicSharedMemorySize, Cfg<0>::SMEM);
    cudaFuncSetAttribute(gemm_hmma<1>, cudaFuncAttributeMaxDynamicSharedMemorySize, Cfg<1>::SMEM);
    cudaFuncSetAttribute(gemm_hmma<2>, cudaFuncAttributeMaxDynamicSharedMemorySize, Cfg<2>::SMEM);

    preamble<<<H_ * S_ + CVT_BLOCKS, 256>>>(s_bias, hidden, v_w, out_w);

    gemm_hmma<0><<<dim3(8, 73),     Cfg<0>::NTH, Cfg<0>::SMEM>>>(v_b, nullptr);
    gemm_hmma<1><<<dim3(8, 10, 16), Cfg<1>::NTH, Cfg<1>::SMEM>>>(nullptr, nullptr);
    gemm_hmma<2><<<dim3(8, 73),     Cfg<2>::NTH, Cfg<2>::SMEM>>>(out_b, out);
}

// round 15
// speedup vs baseline: 1.3230x; 1.0139x over previous
#include <cuda_runtime.h>
#include <cuda_fp16.h>
#include <cstdint>

#define B_ 16
#define S_ 577
#define SP 640               // padded seq (K padding for GEMM2)
#define E_ 1024
#define H_ 16
#define D_ 64
#define M_ (B_ * S_)         // 9232

// ---------------- scratch (static device globals, zero-init at load) -------
__device__ half g_Ah[(size_t)M_ * E_];                   // hidden fp16
__device__ half g_Wv[(size_t)E_ * E_];                   // v_w fp16
__device__ half g_Wo[(size_t)E_ * E_];                   // out_w fp16
__device__ half g_Vh[(size_t)H_ * E_ * SP];              // V^T [h][(b,d)][s] (pad=0)
__device__ half g_Ph[(size_t)H_ * S_ * SP];              // softmax(P) (pad=0)
__device__ half g_Oh[(size_t)M_ * E_];                   // attn out fp16

// ---------------- PTX helpers (portable sm_80-level) ------------------------
__device__ __forceinline__ uint32_t smem_u32(const void* p) {
    uint32_t a;
    asm("{ .reg .u64 t; cvta.to.shared.u64 t, %1; cvt.u32.u64 %0, t; }" : "=r"(a) : "l"(p));
    return a;
}
__device__ __forceinline__ void cp16(uint32_t dst, const void* src) {
    asm volatile("cp.async.cg.shared.global [%0], [%1], 16;" :: "r"(dst), "l"(src));
}
#define CP_COMMIT() asm volatile("cp.async.commit_group;" ::: "memory")
template <int N>
__device__ __forceinline__ void cp_wait() {
    asm volatile("cp.async.wait_group %0;" :: "n"(N) : "memory");
}

__device__ __forceinline__ void ldsm4(uint32_t* r, uint32_t addr) {
    asm volatile("ldmatrix.sync.aligned.m8n8.x4.shared.b16 {%0,%1,%2,%3}, [%4];"
                 : "=r"(r[0]), "=r"(r[1]), "=r"(r[2]), "=r"(r[3]) : "r"(addr));
}
__device__ __forceinline__ void mma_f16(float* c, const uint32_t* a, const uint32_t* b) {
    asm volatile("mma.sync.aligned.m16n8k16.row.col.f32.f16.f16.f32 "
                 "{%0,%1,%2,%3}, {%4,%5,%6,%7}, {%8,%9}, {%0,%1,%2,%3};"
                 : "+f"(c[0]), "+f"(c[1]), "+f"(c[2]), "+f"(c[3])
                 : "r"(a[0]), "r"(a[1]), "r"(a[2]), "r"(a[3]), "r"(b[0]), "r"(b[1]));
}

// ---------------- tiling ----------------------------------------------------
// Crossbar model (validated R12-R14): LDSM B/MAC = 2(WM+WN)/(WM*WN); budget
// = 0.125 B/MAC. All modes now use 4-warp CTAs with warp tiles under budget:
// MODE 0/2: CTA 128x128, warps 64x64 (0.063+0.023), 2 CTA/SM   [R14: 61.6%]
// MODE 1:   CTA  64x128, warps 32x64 (0.094+0.023), 3 CTA/SM   [was 32x32 =
//           0.156 B/MAC, 25% over budget — this round's fix]
// All: 3 stages, SINGLE sync/iter, prefetch dist 2 ((kt+2)%3==(kt-1)%3).
// Row = 8 x 16B chunks, physical chunk = c ^ (row&7): conflict-free ldmatrix.
#define KBLK 64

__device__ __forceinline__ uint32_t swz(int row, int c) {
    return (uint32_t)(row * 128 + ((c ^ (row & 7)) << 4));
}

template <int MODE> struct Cfg {
    static constexpr int NTH = 128;                      // 4 warps, 2x2 grid
    static constexpr int BM  = (MODE == 1) ? 64 : 128;
    static constexpr int BN  = 128;
    static constexpr int WMR = BM / 2;                   // 32 / 64
    static constexpr int WNC = 64;
    static constexpr int MT  = WMR / 16;                 // 2 / 4
    static constexpr int NT  = 8;
    static constexpr int A_BYTES = BM * 128;
    static constexpr int STAGE = A_BYTES + BN * 128;
    static constexpr int SMEM = 3 * STAGE;               // 73728 / 98304
    static constexpr int OCC = (MODE == 1) ? 3 : 2;
    static constexpr int NCHUNK = (BM + BN) * 8 / NTH;   // 12 / 16
};

// ---------------------------------------------------------------------------
// fp16 HMMA GEMM, NT: C[m,n] = sum_k A[m,k]*B[n,k]
// MODE 0: V-proj   A=g_Ah, B=g_Wv, K=1024 -> g_Vh (V^T scatter, +v_b)
// MODE 1: P@V      A=g_Ph, B=g_Vh, K=640  -> g_Oh
// MODE 2: out-proj A=g_Oh, B=g_Wo, K=1024 -> d_out fp32 (+out_b)
// ---------------------------------------------------------------------------
template <int MODE>
__global__ __launch_bounds__(Cfg<MODE>::NTH, Cfg<MODE>::OCC)
void gemm_hmma(const float* __restrict__ bias, float* __restrict__ outp)
{
    using C = Cfg<MODE>;
    extern __shared__ __align__(1024) char smem[];
    const uint32_t sb = smem_u32(smem);
    const int tid  = threadIdx.x;
    const int wid  = tid >> 5, lane = tid & 31;
    const int wm   = wid & 1, wn = wid >> 1;      // 2x2 warp grid
    const int gid  = lane >> 2, tig = lane & 3;

    const half *Ah, *Bh;
    int Mrows, pitch, kiter;
    if (MODE == 0) {
        Ah = g_Ah; Bh = g_Wv;
        Mrows = M_; pitch = E_; kiter = E_ / KBLK;
    } else if (MODE == 1) {
        const size_t ho = (size_t)blockIdx.z;
        Ah = g_Ph + ho * S_ * SP;
        Bh = g_Vh + ho * E_ * SP;
        Mrows = S_; pitch = SP; kiter = SP / KBLK;
    } else {
        Ah = g_Oh; Bh = g_Wo;
        Mrows = M_; pitch = E_; kiter = E_ / KBLK;
    }
    const int tm0 = blockIdx.y * C::BM, tn0 = blockIdx.x * C::BN;

    auto do_load = [&](int kt) {
        if (kt < kiter) {
            const uint32_t sbase = sb + (uint32_t)(kt % 3) * C::STAGE;
            const int koff = kt * KBLK;
#pragma unroll
            for (int p = 0; p < C::NCHUNK; p++) {
                const int id = p * C::NTH + tid;
                if (id < C::BM * 8) {              // A chunk
                    const int row = id >> 3, c = id & 7;
                    int grow = tm0 + row;
                    if (grow >= Mrows) grow = 0;   // clamp: never stored
                    cp16(sbase + swz(row, c),
                         Ah + (size_t)grow * pitch + koff + c * 8);
                } else {                           // B chunk (N=1024 exact)
                    const int idb = id - C::BM * 8;
                    const int row = idb >> 3, c = idb & 7;
                    cp16(sbase + (uint32_t)C::A_BYTES + swz(row, c),
                         Bh + (size_t)(tn0 + row) * pitch + koff + c * 8);
                }
            }
        }
        CP_COMMIT();
    };

    float acc[C::MT][C::NT][4];
#pragma unroll
    for (int i = 0; i < C::MT; i++)
#pragma unroll
        for (int j = 0; j < C::NT; j++)
#pragma unroll
            for (int q = 0; q < 4; q++) acc[i][j][q] = 0.f;

    do_load(0); do_load(1);

    for (int kt = 0; kt < kiter; kt++) {
        cp_wait<1>();
        __syncthreads();
        do_load(kt + 2);                           // (kt+2)%3==(kt-1)%3: done
        const uint32_t Ab = sb + (uint32_t)(kt % 3) * C::STAGE;
        const uint32_t Bb = Ab + C::A_BYTES;

#pragma unroll
        for (int ks = 0; ks < 4; ks++) {           // 4 x k16 slices per k64
            // B fragments via ldmatrix.x4: lanes 0-7 -> (nt,k0), 8-15 ->
            // (nt,k1), 16-23 -> (nt+1,k0), 24-31 -> (nt+1,k1)
            uint32_t bf[C::NT * 2];
#pragma unroll
            for (int ntp = 0; ntp < C::NT / 2; ntp++) {
                const int nr = wn * C::WNC + (ntp * 2 + ((lane >> 4) & 1)) * 8
                               + (lane & 7);
                const int c  = ks * 2 + ((lane >> 3) & 1);
                ldsm4(&bf[ntp * 4], Bb + swz(nr, c));
            }
#pragma unroll
            for (int mt = 0; mt < C::MT; mt++) {
                uint32_t ah[4];
                {
                    const int mr = wm * C::WMR + mt * 16 + (lane & 15);
                    const int kh = lane >> 4;
                    ldsm4(ah, Ab + swz(mr, ks * 2 + kh));
                }
#pragma unroll
                for (int nt = 0; nt < C::NT; nt++)
                    mma_f16(acc[mt][nt], ah, &bf[nt * 2]);
            }
        }
    }

    // ---------------- epilogue ----------------------------------------------
#pragma unroll
    for (int mt = 0; mt < C::MT; mt++) {
#pragma unroll
        for (int half_ = 0; half_ < 2; half_++) {
            const int m = tm0 + wm * C::WMR + mt * 16 + gid + half_ * 8;
            if (m >= Mrows) continue;
            int bb = 0, s = 0;
            if (MODE == 0) { bb = m / S_; s = m - bb * S_; }
#pragma unroll
            for (int nt = 0; nt < C::NT; nt++) {
                const int n0 = tn0 + wn * C::WNC + nt * 8 + tig * 2;
                const float v0 = acc[mt][nt][half_ * 2 + 0];
                const float v1 = acc[mt][nt][half_ * 2 + 1];
                if (MODE == 0) {
                    // scatter: n-neighbors are SP apart -> scalar stores
#pragma unroll
                    for (int j = 0; j < 2; j++) {
                        const int n = n0 + j;
                        const float v = (j ? v1 : v0) + bias[n];
                        const size_t a = ((size_t)(n >> 6) * (B_ * D_)
                                          + (size_t)bb * D_ + (n & 63)) * SP + s;
                        g_Vh[a] = __float2half_rn(v);
                    }
                } else if (MODE == 1) {
                    const size_t a = ((size_t)(n0 >> 6) * S_ + m) * E_
                                     + (size_t)blockIdx.z * D_ + (n0 & 63);
                    *(__half2*)(g_Oh + a) = __floats2half2_rn(v0, v1);
                } else {
                    float2 o;
                    o.x = v0 + bias[n0];
                    o.y = v1 + bias[n0 + 1];
                    *(float2*)(outp + (size_t)m * E_ + n0) = o;
                }
            }
        }
    }
}

// ---------------------------------------------------------------------------
// Fused preamble: blocks [0, H*S) do softmax rows -> g_Ph; the rest do
// float4-vectorized fp32->fp16 conversion (hidden, v_w, out_w).
// Q path cancels: softmax is shift-invariant along the last axis.
// ---------------------------------------------------------------------------
#define CVT_BLOCKS 2960
__device__ __forceinline__ void cvt4(half* dst, const float* src, size_t i4) {
    const float4 v = *(const float4*)(src + i4 * 4);
    __half2 lo = __floats2half2_rn(v.x, v.y);
    __half2 hi = __floats2half2_rn(v.z, v.w);
    uint2 o;
    o.x = *(uint32_t*)&lo;
    o.y = *(uint32_t*)&hi;
    *(uint2*)(dst + i4 * 4) = o;
}

__global__ __launch_bounds__(256)
void preamble(const float* __restrict__ sbias,
              const float* __restrict__ hid,
              const float* __restrict__ vw,
              const float* __restrict__ ow)
{
    const int tid = threadIdx.x;
    if (blockIdx.x < H_ * S_) {
        const int row = blockIdx.x;
        const float* __restrict__ src = sbias + (size_t)row * S_;
        half* __restrict__ dh = g_Ph + (size_t)row * SP;

        __shared__ float shm[8], shs[8];

        float v0 = (tid       < S_) ? src[tid]       : -3.0e38f;
        float v1 = (tid + 256 < S_) ? src[tid + 256] : -3.0e38f;
        float v2 = (tid + 512 < S_) ? src[tid + 512] : -3.0e38f;

        float mx = fmaxf(v0, fmaxf(v1, v2));
#pragma unroll
        for (int o = 16; o > 0; o >>= 1) mx = fmaxf(mx, __shfl_xor_sync(0xffffffffu, mx, o));
        if ((tid & 31) == 0) shm[tid >> 5] = mx;
        __syncthreads();
        mx = shm[0];
#pragma unroll
        for (int w = 1; w < 8; w++) mx = fmaxf(mx, shm[w]);

        float e0 = __expf(v0 - mx), e1 = __expf(v1 - mx), e2 = __expf(v2 - mx);
        float s = e0 + e1 + e2;
#pragma unroll
        for (int o = 16; o > 0; o >>= 1) s += __shfl_xor_sync(0xffffffffu, s, o);
        if ((tid & 31) == 0) shs[tid >> 5] = s;
        __syncthreads();
        s = shs[0];
#pragma unroll
        for (int w = 1; w < 8; w++) s += shs[w];
        const float inv = 1.0f / s;

#pragma unroll
        for (int q = 0; q < 3; q++) {
            const int c = tid + q * 256;
            if (c < SP) {
                const float pv = (c < S_) ? (q == 0 ? e0 : q == 1 ? e1 : e2) * inv : 0.f;
                dh[c] = __float2half_rn(pv);
            }
        }
    } else {
        // float4 conversions; all segment sizes divisible by 4
        const size_t NH4 = (size_t)M_ * E_ / 4;
        const size_t NW4 = (size_t)E_ * E_ / 4;
        const size_t total = NH4 + 2 * NW4;
        const size_t stride = (size_t)CVT_BLOCKS * 256;
        size_t i = (size_t)(blockIdx.x - H_ * S_) * 256 + tid;
        for (; i < total; i += stride) {
            if (i < NH4)            cvt4(g_Ah, hid, i);
            else if (i < NH4 + NW4) cvt4(g_Wv, vw, i - NH4);
            else                    cvt4(g_Wo, ow, i - NH4 - NW4);
        }
    }
}

// ---------------------------------------------------------------------------
extern "C" void kernel_launch(void* const* d_in, const int* in_sizes, int n_in,
                              void* d_out, int out_size)
{
    const float* hidden = (const float*)d_in[0];
    const float* v_w    = (const float*)d_in[3];
    const float* v_b    = (const float*)d_in[4];
    const float* out_w  = (const float*)d_in[5];
    const float* out_b  = (const float*)d_in[6];
    const float* s_bias = (const float*)d_in[8];
    float* out = (float*)d_out;

    cudaFuncSetAttribute(gemm_hmma<0>, cudaFuncAttributeMaxDynamicSharedMemorySize, Cfg<0>::SMEM);
    cudaFuncSetAttribute(gemm_hmma<1>, cudaFuncAttributeMaxDynamicSharedMemorySize, Cfg<1>::SMEM);
    cudaFuncSetAttribute(gemm_hmma<2>, cudaFuncAttributeMaxDynamicSharedMemorySize, Cfg<2>::SMEM);

    preamble<<<H_ * S_ + CVT_BLOCKS, 256>>>(s_bias, hidden, v_w, out_w);

    gemm_hmma<0><<<dim3(8, 73),     Cfg<0>::NTH, Cfg<0>::SMEM>>>(v_b, nullptr);
    gemm_hmma<1><<<dim3(8, 10, 16), Cfg<1>::NTH, Cfg<1>::SMEM>>>(nullptr, nullptr);
    gemm_hmma<2><<<dim3(8, 73),     Cfg<2>::NTH, Cfg<2>::SMEM>>>(out_b, out);
}

// round 16
// speedup vs baseline: 1.3309x; 1.0060x over previous
#include <cuda_runtime.h>
#include <cuda_fp16.h>
#include <cstdint>

#define B_ 16
#define S_ 577
#define SP 640               // padded seq (K padding for GEMM2)
#define E_ 1024
#define H_ 16
#define D_ 64
#define M_ (B_ * S_)         // 9232

// ---------------- scratch (static device globals, zero-init at load) -------
__device__ half g_Ah[(size_t)M_ * E_];                   // hidden fp16
__device__ half g_Wv[(size_t)E_ * E_];                   // v_w fp16
__device__ half g_Wo[(size_t)E_ * E_];                   // out_w fp16
__device__ half g_Vh[(size_t)H_ * E_ * SP];              // V^T [h][(b,d)][s] (pad=0)
__device__ half g_Ph[(size_t)H_ * S_ * SP];              // softmax(P) (pad=0)
__device__ half g_Oh[(size_t)M_ * E_];                   // attn out fp16

// ---------------- PTX helpers (portable sm_80-level) ------------------------
__device__ __forceinline__ uint32_t smem_u32(const void* p) {
    uint32_t a;
    asm("{ .reg .u64 t; cvta.to.shared.u64 t, %1; cvt.u32.u64 %0, t; }" : "=r"(a) : "l"(p));
    return a;
}
__device__ __forceinline__ void cp16(uint32_t dst, const void* src) {
    asm volatile("cp.async.cg.shared.global [%0], [%1], 16;" :: "r"(dst), "l"(src));
}
#define CP_COMMIT() asm volatile("cp.async.commit_group;" ::: "memory")
template <int N>
__device__ __forceinline__ void cp_wait() {
    asm volatile("cp.async.wait_group %0;" :: "n"(N) : "memory");
}

__device__ __forceinline__ void ldsm4(uint32_t* r, uint32_t addr) {
    asm volatile("ldmatrix.sync.aligned.m8n8.x4.shared.b16 {%0,%1,%2,%3}, [%4];"
                 : "=r"(r[0]), "=r"(r[1]), "=r"(r[2]), "=r"(r[3]) : "r"(addr));
}
__device__ __forceinline__ void mma_f16(float* c, const uint32_t* a, const uint32_t* b) {
    asm volatile("mma.sync.aligned.m16n8k16.row.col.f32.f16.f16.f32 "
                 "{%0,%1,%2,%3}, {%4,%5,%6,%7}, {%8,%9}, {%0,%1,%2,%3};"
                 : "+f"(c[0]), "+f"(c[1]), "+f"(c[2]), "+f"(c[3])
                 : "r"(a[0]), "r"(a[1]), "r"(a[2]), "r"(a[3]), "r"(b[0]), "r"(b[1]));
}

// ---------------- tiling ----------------------------------------------------
// Crossbar model (R12-R15): all warp tiles under the 0.125 B/MAC budget;
// plateau at tensor ~61% is ldsm->mma latency at 2 warps/SMSP. This round:
// manual fragment pipelining (A look-ahead everywhere; B double-buffer in
// MODE 1 where the register budget allows it).
// MODE 0/2: CTA 128x128, 4 warps of 64x64, 2 CTA/SM.
// MODE 1:   CTA  64x128, 4 warps of 32x64, 3 CTA/SM.
// All: 3 stages, single sync/iter, prefetch dist 2 ((kt+2)%3==(kt-1)%3).
// Row = 8 x 16B chunks, physical chunk = c ^ (row&7): conflict-free ldmatrix.
#define KBLK 64

__device__ __forceinline__ uint32_t swz(int row, int c) {
    return (uint32_t)(row * 128 + ((c ^ (row & 7)) << 4));
}

template <int MODE> struct Cfg {
    static constexpr int NTH = 128;                      // 4 warps, 2x2 grid
    static constexpr int BM  = (MODE == 1) ? 64 : 128;
    static constexpr int BN  = 128;
    static constexpr int WMR = BM / 2;                   // 32 / 64
    static constexpr int WNC = 64;
    static constexpr int MT  = WMR / 16;                 // 2 / 4
    static constexpr int NT  = 8;
    static constexpr int A_BYTES = BM * 128;
    static constexpr int STAGE = A_BYTES + BN * 128;
    static constexpr int SMEM = 3 * STAGE;               // 73728 / 98304
    static constexpr int OCC = (MODE == 1) ? 3 : 2;
    static constexpr int NCHUNK = (BM + BN) * 8 / NTH;   // 12 / 16
    static constexpr bool PIPE_B = (MODE == 1);          // reg headroom there
};

// ---------------------------------------------------------------------------
// fp16 HMMA GEMM, NT: C[m,n] = sum_k A[m,k]*B[n,k]
// MODE 0: V-proj   A=g_Ah, B=g_Wv, K=1024 -> g_Vh (V^T scatter, +v_b)
// MODE 1: P@V      A=g_Ph, B=g_Vh, K=640  -> g_Oh
// MODE 2: out-proj A=g_Oh, B=g_Wo, K=1024 -> d_out fp32 (+out_b)
// ---------------------------------------------------------------------------
template <int MODE>
__global__ __launch_bounds__(Cfg<MODE>::NTH, Cfg<MODE>::OCC)
void gemm_hmma(const float* __restrict__ bias, float* __restrict__ outp)
{
    using C = Cfg<MODE>;
    extern __shared__ __align__(1024) char smem[];
    const uint32_t sb = smem_u32(smem);
    const int tid  = threadIdx.x;
    const int wid  = tid >> 5, lane = tid & 31;
    const int wm   = wid & 1, wn = wid >> 1;      // 2x2 warp grid
    const int gid  = lane >> 2, tig = lane & 3;

    const half *Ah, *Bh;
    int Mrows, pitch, kiter;
    if (MODE == 0) {
        Ah = g_Ah; Bh = g_Wv;
        Mrows = M_; pitch = E_; kiter = E_ / KBLK;
    } else if (MODE == 1) {
        const size_t ho = (size_t)blockIdx.z;
        Ah = g_Ph + ho * S_ * SP;
        Bh = g_Vh + ho * E_ * SP;
        Mrows = S_; pitch = SP; kiter = SP / KBLK;
    } else {
        Ah = g_Oh; Bh = g_Wo;
        Mrows = M_; pitch = E_; kiter = E_ / KBLK;
    }
    const int tm0 = blockIdx.y * C::BM, tn0 = blockIdx.x * C::BN;

    auto do_load = [&](int kt) {
        if (kt < kiter) {
            const uint32_t sbase = sb + (uint32_t)(kt % 3) * C::STAGE;
            const int koff = kt * KBLK;
#pragma unroll
            for (int p = 0; p < C::NCHUNK; p++) {
                const int id = p * C::NTH + tid;
                if (id < C::BM * 8) {              // A chunk
                    const int row = id >> 3, c = id & 7;
                    int grow = tm0 + row;
                    if (grow >= Mrows) grow = 0;   // clamp: never stored
                    cp16(sbase + swz(row, c),
                         Ah + (size_t)grow * pitch + koff + c * 8);
                } else {                           // B chunk (N=1024 exact)
                    const int idb = id - C::BM * 8;
                    const int row = idb >> 3, c = idb & 7;
                    cp16(sbase + (uint32_t)C::A_BYTES + swz(row, c),
                         Bh + (size_t)(tn0 + row) * pitch + koff + c * 8);
                }
            }
        }
        CP_COMMIT();
    };

    // B-fragment loader for one k16 slice (16 regs via 4 x ldsm4)
    auto load_b = [&](uint32_t* bf, uint32_t Bb, int ks) {
#pragma unroll
        for (int ntp = 0; ntp < C::NT / 2; ntp++) {
            const int nr = wn * C::WNC + (ntp * 2 + ((lane >> 4) & 1)) * 8
                           + (lane & 7);
            const int c  = ks * 2 + ((lane >> 3) & 1);
            ldsm4(&bf[ntp * 4], Bb + swz(nr, c));
        }
    };

    float acc[C::MT][C::NT][4];
#pragma unroll
    for (int i = 0; i < C::MT; i++)
#pragma unroll
        for (int j = 0; j < C::NT; j++)
#pragma unroll
            for (int q = 0; q < 4; q++) acc[i][j][q] = 0.f;

    do_load(0); do_load(1);

    for (int kt = 0; kt < kiter; kt++) {
        cp_wait<1>();
        __syncthreads();
        do_load(kt + 2);                           // (kt+2)%3==(kt-1)%3: done
        const uint32_t Ab = sb + (uint32_t)(kt % 3) * C::STAGE;
        const uint32_t Bb = Ab + C::A_BYTES;

        uint32_t bfA[C::NT * 2], bfB[C::PIPE_B ? C::NT * 2 : 1];
        if (C::PIPE_B) load_b(bfA, Bb, 0);

#pragma unroll
        for (int ks = 0; ks < 4; ks++) {           // 4 x k16 slices per k64
            uint32_t* cur;
            if (C::PIPE_B) {
                cur = (ks & 1) ? bfB : bfA;
                uint32_t* nxt = (ks & 1) ? bfA : bfB;
                if (ks < 3) load_b(nxt, Bb, ks + 1);   // hide under MMAs
            } else {
                cur = bfA;
                load_b(cur, Bb, ks);
            }

            // A-fragment look-ahead: load mt+1 while issuing mt's MMAs
            uint32_t ah0[4], ah1[4];
            const int kh = lane >> 4;
            {
                const int mr = wm * C::WMR + (lane & 15);
                ldsm4(ah0, Ab + swz(mr, ks * 2 + kh));
            }
#pragma unroll
            for (int mt = 0; mt < C::MT; mt++) {
                uint32_t* ca = (mt & 1) ? ah1 : ah0;
                uint32_t* na = (mt & 1) ? ah0 : ah1;
                if (mt + 1 < C::MT) {
                    const int mr = wm * C::WMR + (mt + 1) * 16 + (lane & 15);
                    ldsm4(na, Ab + swz(mr, ks * 2 + kh));
                }
#pragma unroll
                for (int nt = 0; nt < C::NT; nt++)
                    mma_f16(acc[mt][nt], ca, &cur[nt * 2]);
            }
        }
    }

    // ---------------- epilogue ----------------------------------------------
#pragma unroll
    for (int mt = 0; mt < C::MT; mt++) {
#pragma unroll
        for (int half_ = 0; half_ < 2; half_++) {
            const int m = tm0 + wm * C::WMR + mt * 16 + gid + half_ * 8;
            if (m >= Mrows) continue;
            int bb = 0, s = 0;
            if (MODE == 0) { bb = m / S_; s = m - bb * S_; }
#pragma unroll
            for (int nt = 0; nt < C::NT; nt++) {
                const int n0 = tn0 + wn * C::WNC + nt * 8 + tig * 2;
                const float v0 = acc[mt][nt][half_ * 2 + 0];
                const float v1 = acc[mt][nt][half_ * 2 + 1];
                if (MODE == 0) {
                    // scatter: n-neighbors are SP apart -> scalar stores
#pragma unroll
                    for (int j = 0; j < 2; j++) {
                        const int n = n0 + j;
                        const float v = (j ? v1 : v0) + bias[n];
                        const size_t a = ((size_t)(n >> 6) * (B_ * D_)
                                          + (size_t)bb * D_ + (n & 63)) * SP + s;
                        g_Vh[a] = __float2half_rn(v);
                    }
                } else if (MODE == 1) {
                    const size_t a = ((size_t)(n0 >> 6) * S_ + m) * E_
                                     + (size_t)blockIdx.z * D_ + (n0 & 63);
                    *(__half2*)(g_Oh + a) = __floats2half2_rn(v0, v1);
                } else {
                    float2 o;
                    o.x = v0 + bias[n0];
                    o.y = v1 + bias[n0 + 1];
                    *(float2*)(outp + (size_t)m * E_ + n0) = o;
                }
            }
        }
    }
}

// ---------------------------------------------------------------------------
// Fused preamble: blocks [0, H*S) do softmax rows -> g_Ph; the rest do
// float4-vectorized fp32->fp16 conversion (hidden, v_w, out_w).
// Q path cancels: softmax is shift-invariant along the last axis.
// ---------------------------------------------------------------------------
#define CVT_BLOCKS 5920
__device__ __forceinline__ void cvt4(half* dst, const float* src, size_t i4) {
    const float4 v = *(const float4*)(src + i4 * 4);
    __half2 lo = __floats2half2_rn(v.x, v.y);
    __half2 hi = __floats2half2_rn(v.z, v.w);
    uint2 o;
    o.x = *(uint32_t*)&lo;
    o.y = *(uint32_t*)&hi;
    *(uint2*)(dst + i4 * 4) = o;
}

__global__ __launch_bounds__(256)
void preamble(const float* __restrict__ sbias,
              const float* __restrict__ hid,
              const float* __restrict__ vw,
              const float* __restrict__ ow)
{
    const int tid = threadIdx.x;
    if (blockIdx.x < H_ * S_) {
        const int row = blockIdx.x;
        const float* __restrict__ src = sbias + (size_t)row * S_;
        half* __restrict__ dh = g_Ph + (size_t)row * SP;

        __shared__ float shm[8], shs[8];

        float v0 = (tid       < S_) ? src[tid]       : -3.0e38f;
        float v1 = (tid + 256 < S_) ? src[tid + 256] : -3.0e38f;
        float v2 = (tid + 512 < S_) ? src[tid + 512] : -3.0e38f;

        float mx = fmaxf(v0, fmaxf(v1, v2));
#pragma unroll
        for (int o = 16; o > 0; o >>= 1) mx = fmaxf(mx, __shfl_xor_sync(0xffffffffu, mx, o));
        if ((tid & 31) == 0) shm[tid >> 5] = mx;
        __syncthreads();
        mx = shm[0];
#pragma unroll
        for (int w = 1; w < 8; w++) mx = fmaxf(mx, shm[w]);

        float e0 = __expf(v0 - mx), e1 = __expf(v1 - mx), e2 = __expf(v2 - mx);
        float s = e0 + e1 + e2;
#pragma unroll
        for (int o = 16; o > 0; o >>= 1) s += __shfl_xor_sync(0xffffffffu, s, o);
        if ((tid & 31) == 0) shs[tid >> 5] = s;
        __syncthreads();
        s = shs[0];
#pragma unroll
        for (int w = 1; w < 8; w++) s += shs[w];
        const float inv = 1.0f / s;

#pragma unroll
        for (int q = 0; q < 3; q++) {
            const int c = tid + q * 256;
            if (c < SP) {
                const float pv = (c < S_) ? (q == 0 ? e0 : q == 1 ? e1 : e2) * inv : 0.f;
                dh[c] = __float2half_rn(pv);
            }
        }
    } else {
        // float4 conversions; all segment sizes divisible by 4
        const size_t NH4 = (size_t)M_ * E_ / 4;
        const size_t NW4 = (size_t)E_ * E_ / 4;
        const size_t total = NH4 + 2 * NW4;
        const size_t stride = (size_t)CVT_BLOCKS * 256;
        size_t i = (size_t)(blockIdx.x - H_ * S_) * 256 + tid;
        for (; i < total; i += stride) {
            if (i < NH4)            cvt4(g_Ah, hid, i);
            else if (i < NH4 + NW4) cvt4(g_Wv, vw, i - NH4);
            else                    cvt4(g_Wo, ow, i - NH4 - NW4);
        }
    }
}

// ---------------------------------------------------------------------------
extern "C" void kernel_launch(void* const* d_in, const int* in_sizes, int n_in,
                              void* d_out, int out_size)
{
    const float* hidden = (const float*)d_in[0];
    const float* v_w    = (const float*)d_in[3];
    const float* v_b    = (const float*)d_in[4];
    const float* out_w  = (const float*)d_in[5];
    const float* out_b  = (const float*)d_in[6];
    const float* s_bias = (const float*)d_in[8];
    float* out = (float*)d_out;

    cudaFuncSetAttribute(gemm_hmma<0>, cudaFuncAttributeMaxDynamicSharedMemorySize, Cfg<0>::SMEM);
    cudaFuncSetAttribute(gemm_hmma<1>, cudaFuncAttributeMaxDynamicSharedMemorySize, Cfg<1>::SMEM);
    cudaFuncSetAttribute(gemm_hmma<2>, cudaFuncAttributeMaxDynamicSharedMemorySize, Cfg<2>::SMEM);

    preamble<<<H_ * S_ + CVT_BLOCKS, 256>>>(s_bias, hidden, v_w, out_w);

    gemm_hmma<0><<<dim3(8, 73),     Cfg<0>::NTH, Cfg<0>::SMEM>>>(v_b, nullptr);
    gemm_hmma<1><<<dim3(8, 10, 16), Cfg<1>::NTH, Cfg<1>::SMEM>>>(nullptr, nullptr);
    gemm_hmma<2><<<dim3(8, 73),     Cfg<2>::NTH, Cfg<2>::SMEM>>>(out_b, out);
}

// round 17
// speedup vs baseline: 1.3709x; 1.0300x over previous
#include <cuda_runtime.h>
#include <cuda_fp16.h>
#include <cstdint>

#define B_ 16
#define S_ 577
#define SP 640               // padded seq (K padding for GEMM2)
#define E_ 1024
#define H_ 16
#define D_ 64
#define M_ (B_ * S_)         // 9232

// ---------------- scratch (static device globals, zero-init at load) -------
__device__ half g_Ah[(size_t)M_ * E_];                   // hidden fp16
__device__ half g_Wv[(size_t)E_ * E_];                   // v_w fp16
__device__ half g_Wo[(size_t)E_ * E_];                   // out_w fp16
__device__ half g_Vh[(size_t)H_ * E_ * SP];              // V^T [h][(b,d)][s] (pad=0)
__device__ half g_Ph[(size_t)H_ * S_ * SP];              // softmax(P); pad cols stay 0
__device__ half g_Oh[(size_t)M_ * E_];                   // attn out fp16

// ---------------- PTX helpers (portable sm_80-level) ------------------------
__device__ __forceinline__ uint32_t smem_u32(const void* p) {
    uint32_t a;
    asm("{ .reg .u64 t; cvta.to.shared.u64 t, %1; cvt.u32.u64 %0, t; }" : "=r"(a) : "l"(p));
    return a;
}
__device__ __forceinline__ void cp16(uint32_t dst, const void* src) {
    asm volatile("cp.async.cg.shared.global [%0], [%1], 16;" :: "r"(dst), "l"(src));
}
#define CP_COMMIT() asm volatile("cp.async.commit_group;" ::: "memory")
template <int N>
__device__ __forceinline__ void cp_wait() {
    asm volatile("cp.async.wait_group %0;" :: "n"(N) : "memory");
}

__device__ __forceinline__ void ldsm4(uint32_t* r, uint32_t addr) {
    asm volatile("ldmatrix.sync.aligned.m8n8.x4.shared.b16 {%0,%1,%2,%3}, [%4];"
                 : "=r"(r[0]), "=r"(r[1]), "=r"(r[2]), "=r"(r[3]) : "r"(addr));
}
__device__ __forceinline__ void mma_f16(float* c, const uint32_t* a, const uint32_t* b) {
    asm volatile("mma.sync.aligned.m16n8k16.row.col.f32.f16.f16.f32 "
                 "{%0,%1,%2,%3}, {%4,%5,%6,%7}, {%8,%9}, {%0,%1,%2,%3};"
                 : "+f"(c[0]), "+f"(c[1]), "+f"(c[2]), "+f"(c[3])
                 : "r"(a[0]), "r"(a[1]), "r"(a[2]), "r"(a[3]), "r"(b[0]), "r"(b[1]));
}

// ---------------- tiling (R16-verified; GEMMs at mma.sync ceiling ~62%) -----
// MODE 0/2: CTA 128x128, 4 warps of 64x64, 2 CTA/SM.
// MODE 1:   CTA  64x128, 4 warps of 32x64, 3 CTA/SM.
// All: 3 stages, single sync/iter, prefetch dist 2 ((kt+2)%3==(kt-1)%3).
// Row = 8 x 16B chunks, physical chunk = c ^ (row&7): conflict-free ldmatrix.
#define KBLK 64

__device__ __forceinline__ uint32_t swz(int row, int c) {
    return (uint32_t)(row * 128 + ((c ^ (row & 7)) << 4));
}

template <int MODE> struct Cfg {
    static constexpr int NTH = 128;                      // 4 warps, 2x2 grid
    static constexpr int BM  = (MODE == 1) ? 64 : 128;
    static constexpr int BN  = 128;
    static constexpr int WMR = BM / 2;                   // 32 / 64
    static constexpr int WNC = 64;
    static constexpr int MT  = WMR / 16;                 // 2 / 4
    static constexpr int NT  = 8;
    static constexpr int A_BYTES = BM * 128;
    static constexpr int STAGE = A_BYTES + BN * 128;
    static constexpr int SMEM = 3 * STAGE;               // 73728 / 98304
    static constexpr int OCC = (MODE == 1) ? 3 : 2;
    static constexpr int NCHUNK = (BM + BN) * 8 / NTH;   // 12 / 16
    static constexpr bool PIPE_B = (MODE == 1);
};

// ---------------------------------------------------------------------------
// fp16 HMMA GEMM, NT: C[m,n] = sum_k A[m,k]*B[n,k]
// MODE 0: V-proj   A=g_Ah, B=g_Wv, K=1024 -> g_Vh (V^T scatter, +v_b)
// MODE 1: P@V      A=g_Ph, B=g_Vh, K=640  -> g_Oh
// MODE 2: out-proj A=g_Oh, B=g_Wo, K=1024 -> d_out fp32 (+out_b)
// ---------------------------------------------------------------------------
template <int MODE>
__global__ __launch_bounds__(Cfg<MODE>::NTH, Cfg<MODE>::OCC)
void gemm_hmma(const float* __restrict__ bias, float* __restrict__ outp)
{
    using C = Cfg<MODE>;
    extern __shared__ __align__(1024) char smem[];
    const uint32_t sb = smem_u32(smem);
    const int tid  = threadIdx.x;
    const int wid  = tid >> 5, lane = tid & 31;
    const int wm   = wid & 1, wn = wid >> 1;      // 2x2 warp grid
    const int gid  = lane >> 2, tig = lane & 3;

    const half *Ah, *Bh;
    int Mrows, pitch, kiter;
    if (MODE == 0) {
        Ah = g_Ah; Bh = g_Wv;
        Mrows = M_; pitch = E_; kiter = E_ / KBLK;
    } else if (MODE == 1) {
        const size_t ho = (size_t)blockIdx.z;
        Ah = g_Ph + ho * S_ * SP;
        Bh = g_Vh + ho * E_ * SP;
        Mrows = S_; pitch = SP; kiter = SP / KBLK;
    } else {
        Ah = g_Oh; Bh = g_Wo;
        Mrows = M_; pitch = E_; kiter = E_ / KBLK;
    }
    const int tm0 = blockIdx.y * C::BM, tn0 = blockIdx.x * C::BN;

    auto do_load = [&](int kt) {
        if (kt < kiter) {
            const uint32_t sbase = sb + (uint32_t)(kt % 3) * C::STAGE;
            const int koff = kt * KBLK;
#pragma unroll
            for (int p = 0; p < C::NCHUNK; p++) {
                const int id = p * C::NTH + tid;
                if (id < C::BM * 8) {              // A chunk
                    const int row = id >> 3, c = id & 7;
                    int grow = tm0 + row;
                    if (grow >= Mrows) grow = 0;   // clamp: never stored
                    cp16(sbase + swz(row, c),
                         Ah + (size_t)grow * pitch + koff + c * 8);
                } else {                           // B chunk (N=1024 exact)
                    const int idb = id - C::BM * 8;
                    const int row = idb >> 3, c = idb & 7;
                    cp16(sbase + (uint32_t)C::A_BYTES + swz(row, c),
                         Bh + (size_t)(tn0 + row) * pitch + koff + c * 8);
                }
            }
        }
        CP_COMMIT();
    };

    // B-fragment loader for one k16 slice (16 regs via 4 x ldsm4)
    auto load_b = [&](uint32_t* bf, uint32_t Bb, int ks) {
#pragma unroll
        for (int ntp = 0; ntp < C::NT / 2; ntp++) {
            const int nr = wn * C::WNC + (ntp * 2 + ((lane >> 4) & 1)) * 8
                           + (lane & 7);
            const int c  = ks * 2 + ((lane >> 3) & 1);
            ldsm4(&bf[ntp * 4], Bb + swz(nr, c));
        }
    };

    float acc[C::MT][C::NT][4];
#pragma unroll
    for (int i = 0; i < C::MT; i++)
#pragma unroll
        for (int j = 0; j < C::NT; j++)
#pragma unroll
            for (int q = 0; q < 4; q++) acc[i][j][q] = 0.f;

    do_load(0); do_load(1);

    for (int kt = 0; kt < kiter; kt++) {
        cp_wait<1>();
        __syncthreads();
        do_load(kt + 2);                           // (kt+2)%3==(kt-1)%3: done
        const uint32_t Ab = sb + (uint32_t)(kt % 3) * C::STAGE;
        const uint32_t Bb = Ab + C::A_BYTES;

        uint32_t bfA[C::NT * 2], bfB[C::PIPE_B ? C::NT * 2 : 1];
        if (C::PIPE_B) load_b(bfA, Bb, 0);

#pragma unroll
        for (int ks = 0; ks < 4; ks++) {           // 4 x k16 slices per k64
            uint32_t* cur;
            if (C::PIPE_B) {
                cur = (ks & 1) ? bfB : bfA;
                uint32_t* nxt = (ks & 1) ? bfA : bfB;
                if (ks < 3) load_b(nxt, Bb, ks + 1);   // hide under MMAs
            } else {
                cur = bfA;
                load_b(cur, Bb, ks);
            }

            uint32_t ah0[4], ah1[4];
            const int kh = lane >> 4;
            {
                const int mr = wm * C::WMR + (lane & 15);
                ldsm4(ah0, Ab + swz(mr, ks * 2 + kh));
            }
#pragma unroll
            for (int mt = 0; mt < C::MT; mt++) {
                uint32_t* ca = (mt & 1) ? ah1 : ah0;
                uint32_t* na = (mt & 1) ? ah0 : ah1;
                if (mt + 1 < C::MT) {
                    const int mr = wm * C::WMR + (mt + 1) * 16 + (lane & 15);
                    ldsm4(na, Ab + swz(mr, ks * 2 + kh));
                }
#pragma unroll
                for (int nt = 0; nt < C::NT; nt++)
                    mma_f16(acc[mt][nt], ca, &cur[nt * 2]);
            }
        }
    }

    // ---------------- epilogue ----------------------------------------------
#pragma unroll
    for (int mt = 0; mt < C::MT; mt++) {
#pragma unroll
        for (int half_ = 0; half_ < 2; half_++) {
            const int m = tm0 + wm * C::WMR + mt * 16 + gid + half_ * 8;
            if (m >= Mrows) continue;
            int bb = 0, s = 0;
            if (MODE == 0) { bb = m / S_; s = m - bb * S_; }
#pragma unroll
            for (int nt = 0; nt < C::NT; nt++) {
                const int n0 = tn0 + wn * C::WNC + nt * 8 + tig * 2;
                const float v0 = acc[mt][nt][half_ * 2 + 0];
                const float v1 = acc[mt][nt][half_ * 2 + 1];
                if (MODE == 0) {
                    // scatter: n-neighbors are SP apart -> scalar stores
#pragma unroll
                    for (int j = 0; j < 2; j++) {
                        const int n = n0 + j;
                        const float v = (j ? v1 : v0) + bias[n];
                        const size_t a = ((size_t)(n >> 6) * (B_ * D_)
                                          + (size_t)bb * D_ + (n & 63)) * SP + s;
                        g_Vh[a] = __float2half_rn(v);
                    }
                } else if (MODE == 1) {
                    const size_t a = ((size_t)(n0 >> 6) * S_ + m) * E_
                                     + (size_t)blockIdx.z * D_ + (n0 & 63);
                    *(__half2*)(g_Oh + a) = __floats2half2_rn(v0, v1);
                } else {
                    float2 o;
                    o.x = v0 + bias[n0];
                    o.y = v1 + bias[n0 + 1];
                    *(float2*)(outp + (size_t)m * E_ + n0) = o;
                }
            }
        }
    }
}

// ---------------------------------------------------------------------------
// Fused preamble v2:
//  blocks [0, SMX_BLOCKS): warp-per-row softmax (sync-free, full row in regs)
//  blocks [SMX_BLOCKS, +CVT_BLOCKS): float4 fp32->fp16 cvt (hidden, v_w, out_w)
// Q path cancels: softmax is shift-invariant along the last axis.
// g_Ph pad cols [577,640) are never written (zero from static init).
// ---------------------------------------------------------------------------
#define SMX_BLOCKS (H_ * S_ / 8)      // 1154 blocks x 8 warps = 9232 rows
#define CVT_BLOCKS 5920
#define NLD 19                        // ceil(577/32)

__device__ __forceinline__ void cvt4(half* dst, const float* src, size_t i4) {
    const float4 v = *(const float4*)(src + i4 * 4);
    __half2 lo = __floats2half2_rn(v.x, v.y);
    __half2 hi = __floats2half2_rn(v.z, v.w);
    uint2 o;
    o.x = *(uint32_t*)&lo;
    o.y = *(uint32_t*)&hi;
    *(uint2*)(dst + i4 * 4) = o;
}

__global__ __launch_bounds__(256)
void preamble(const float* __restrict__ sbias,
              const float* __restrict__ hid,
              const float* __restrict__ vw,
              const float* __restrict__ ow)
{
    const int tid = threadIdx.x;
    if (blockIdx.x < SMX_BLOCKS) {
        // ---- warp-per-row softmax, no barriers ----
        const int lane = tid & 31;
        const int row  = blockIdx.x * 8 + (tid >> 5);
        const float* __restrict__ src = sbias + (size_t)row * S_;
        half* __restrict__ dh = g_Ph + (size_t)row * SP;

        float v[NLD];
        float mx = -3.0e38f;
#pragma unroll
        for (int i = 0; i < NLD; i++) {
            const int c = lane + i * 32;
            v[i] = (c < S_) ? src[c] : -3.0e38f;
            mx = fmaxf(mx, v[i]);
        }
#pragma unroll
        for (int o = 16; o > 0; o >>= 1)
            mx = fmaxf(mx, __shfl_xor_sync(0xffffffffu, mx, o));

        float s = 0.f;
#pragma unroll
        for (int i = 0; i < NLD; i++) {
            v[i] = __expf(v[i] - mx);      // pad lanes: exp(-inf) = 0
            s += v[i];
        }
#pragma unroll
        for (int o = 16; o > 0; o >>= 1)
            s += __shfl_xor_sync(0xffffffffu, s, o);
        const float inv = 1.0f / s;

#pragma unroll
        for (int i = 0; i < NLD; i++) {
            const int c = lane + i * 32;
            if (c < S_) dh[c] = __float2half_rn(v[i] * inv);
        }
    } else {
        // ---- float4 conversions; all segment sizes divisible by 4 ----
        const size_t NH4 = (size_t)M_ * E_ / 4;
        const size_t NW4 = (size_t)E_ * E_ / 4;
        const size_t total = NH4 + 2 * NW4;
        const size_t stride = (size_t)CVT_BLOCKS * 256;
        size_t i = (size_t)(blockIdx.x - SMX_BLOCKS) * 256 + tid;
        for (; i < total; i += stride) {
            if (i < NH4)            cvt4(g_Ah, hid, i);
            else if (i < NH4 + NW4) cvt4(g_Wv, vw, i - NH4);
            else                    cvt4(g_Wo, ow, i - NH4 - NW4);
        }
    }
}

// ---------------------------------------------------------------------------
extern "C" void kernel_launch(void* const* d_in, const int* in_sizes, int n_in,
                              void* d_out, int out_size)
{
    const float* hidden = (const float*)d_in[0];
    const float* v_w    = (const float*)d_in[3];
    const float* v_b    = (const float*)d_in[4];
    const float* out_w  = (const float*)d_in[5];
    const float* out_b  = (const float*)d_in[6];
    const float* s_bias = (const float*)d_in[8];
    float* out = (float*)d_out;

    cudaFuncSetAttribute(gemm_hmma<0>, cudaFuncAttributeMaxDynamicSharedMemorySize, Cfg<0>::SMEM);
    cudaFuncSetAttribute(gemm_hmma<1>, cudaFuncAttributeMaxDynamicSharedMemorySize, Cfg<1>::SMEM);
    cudaFuncSetAttribute(gemm_hmma<2>, cudaFuncAttributeMaxDynamicSharedMemorySize, Cfg<2>::SMEM);

    preamble<<<SMX_BLOCKS + CVT_BLOCKS, 256>>>(s_bias, hidden, v_w, out_w);

    gemm_hmma<0><<<dim3(8, 73),     Cfg<0>::NTH, Cfg<0>::SMEM>>>(v_b, nullptr);
    gemm_hmma<1><<<dim3(8, 10, 16), Cfg<1>::NTH, Cfg<1>::SMEM>>>(nullptr, nullptr);
    gemm_hmma<2><<<dim3(8, 73),     Cfg<2>::NTH, Cfg<2>::SMEM>>>(out_b, out);
}